// round 2
// baseline (speedup 1.0000x reference)
#include <cuda_runtime.h>
#include <cstdint>

// Problem constants (from reference)
#define NN      50000
#define EE      800000
#define FD      128
#define GG      64
#define OUTD    64
#define NEXP    3
#define TEMP_F  101.0f
#define POOL_SPLITS 16

// ---------------- device scratch (no cudaMalloc allowed) ----------------
__device__ float g_dinv[NN];                 // deg, then rsqrt(deg)
__device__ float g_gate0[NN * NEXP];
__device__ float g_gate1[NN * NEXP];
__device__ float g_bufA[NN * FD];            // aggregated features
__device__ float g_bufB[NN * FD];            // layer outputs
__device__ float g_pool[POOL_SPLITS][GG * FD];
__device__ float g_cnt[GG];
__device__ int   g_is64;                     // 1 if indices are int64

// ---------------- helpers ----------------
__device__ __forceinline__ int load_idx(const void* p, long long i) {
    if (g_is64) return (int)((const long long*)p)[i];
    return ((const int*)p)[i];
}

__device__ __forceinline__ void red_add_v4(float* p, float4 v) {
    asm volatile("red.global.add.v4.f32 [%0], {%1,%2,%3,%4};"
                 :: "l"(p), "f"(v.x), "f"(v.y), "f"(v.z), "f"(v.w) : "memory");
}

// ---------------- kernels ----------------

// Detect whether edge_index is int64 (high words of little-endian pairs all 0)
__global__ void detect_kernel(const int* p) {
    if (threadIdx.x == 0 && blockIdx.x == 0) {
        int all0 = 1;
        #pragma unroll
        for (int i = 1; i < 128; i += 2) if (p[i] != 0) all0 = 0;
        g_is64 = all0;
    }
}

__global__ void deg_init_kernel(int n) {
    int i = blockIdx.x * blockDim.x + threadIdx.x;
    if (i < n) g_dinv[i] = 1.0f;  // self loop
}

__global__ void deg_count_kernel(const void* ei, int E) {
    int i = blockIdx.x * blockDim.x + threadIdx.x;
    if (i >= E) return;
    int d = load_idx(ei, (long long)E + i);
    atomicAdd(&g_dinv[d], 1.0f);
}

__global__ void deg_finish_kernel(int n) {
    int i = blockIdx.x * blockDim.x + threadIdx.x;
    if (i < n) g_dinv[i] = rsqrtf(g_dinv[i]);
}

// Both layers' gates: softmax over 3 experts of (top @ Wg.T)/TEMP
__global__ void gates_kernel(const float* __restrict__ top,
                             const float* __restrict__ Wg0,
                             const float* __restrict__ Wg1, int n) {
    int i = blockIdx.x * blockDim.x + threadIdx.x;
    if (i >= n) return;
    float t0 = top[i * 4 + 0], t1 = top[i * 4 + 1];
    float t2 = top[i * 4 + 2], t3 = top[i * 4 + 3];
    const float* wgs[2] = {Wg0, Wg1};
    float* outs[2] = {g_gate0, g_gate1};
    #pragma unroll
    for (int L = 0; L < 2; L++) {
        const float* Wg = wgs[L];
        float l[NEXP];
        #pragma unroll
        for (int e = 0; e < NEXP; e++) {
            l[e] = (t0 * Wg[e * 4 + 0] + t1 * Wg[e * 4 + 1] +
                    t2 * Wg[e * 4 + 2] + t3 * Wg[e * 4 + 3]) * (1.0f / TEMP_F);
        }
        float m = fmaxf(l[0], fmaxf(l[1], l[2]));
        float e0 = __expf(l[0] - m), e1 = __expf(l[1] - m), e2 = __expf(l[2] - m);
        float inv = 1.0f / (e0 + e1 + e2);
        outs[L][i * 3 + 0] = e0 * inv;
        outs[L][i * 3 + 1] = e1 * inv;
        outs[L][i * 3 + 2] = e2 * inv;
    }
}

// out = dinv^2 * h  (self-loop term, also initializes the aggregation buffer)
__global__ void self_init_kernel(const float* __restrict__ h,
                                 float* __restrict__ outv, int n) {
    int id = blockIdx.x * blockDim.x + threadIdx.x;   // over n*32 float4s
    if (id >= n * 32) return;
    int node = id >> 5;
    float s = g_dinv[node];
    s = s * s;
    float4 v = reinterpret_cast<const float4*>(h)[id];
    v.x *= s; v.y *= s; v.z *= s; v.w *= s;
    reinterpret_cast<float4*>(outv)[id] = v;
}

// out[dst] += dinv[src]*dinv[dst]*h[src]  -- one warp per edge, float4 lanes
__global__ void edge_agg_kernel(const float* __restrict__ h,
                                float* __restrict__ outv,
                                const void* __restrict__ ei, int E) {
    int w = (blockIdx.x * blockDim.x + threadIdx.x) >> 5;
    int lane = threadIdx.x & 31;
    if (w >= E) return;
    int s = load_idx(ei, w);
    int d = load_idx(ei, (long long)E + w);
    float nrm = g_dinv[s] * g_dinv[d];
    float4 v = reinterpret_cast<const float4*>(h)[(long long)s * 32 + lane];
    v.x *= nrm; v.y *= nrm; v.z *= nrm; v.w *= nrm;
    red_add_v4(outv + (long long)d * 128 + lane * 4, v);
}

// out[n,:] = sum_e gate[n,e] * relu(A[n,:] @ W[e] + b[e])
// Block: 64 rows x 128 cols; A-tile loaded once, reused across 3 experts.
__global__ void __launch_bounds__(256, 1)
moe_kernel(const float* __restrict__ A, const float* __restrict__ W,
           const float* __restrict__ bias, const float* __restrict__ gate,
           float* __restrict__ out, int n) {
    __shared__ float sA[64 * 128];
    __shared__ float sB[32 * 128];
    const int t = threadIdx.x;
    const int row0 = blockIdx.x * 64;

    // load A tile (64x128) once
    #pragma unroll
    for (int i = 0; i < 8; i++) {
        int id = i * 256 + t;             // float4 index 0..2047
        int r = id >> 5, c4 = id & 31;
        int gr = row0 + r;
        float4 v = make_float4(0.f, 0.f, 0.f, 0.f);
        if (gr < n) v = reinterpret_cast<const float4*>(A)[(long long)gr * 32 + c4];
        reinterpret_cast<float4*>(sA)[id] = v;
    }

    const int tx = t & 15, ty = t >> 4;   // 16x16 thread grid
    const int cb = tx * 8;                // 8 output cols per thread
    float o[4][8];
    #pragma unroll
    for (int i = 0; i < 4; i++)
        #pragma unroll
        for (int j = 0; j < 8; j++) o[i][j] = 0.f;

    for (int e = 0; e < NEXP; e++) {
        float acc[4][8];
        #pragma unroll
        for (int i = 0; i < 4; i++)
            #pragma unroll
            for (int j = 0; j < 8; j++) acc[i][j] = 0.f;

        const float* We = W + e * (FD * FD);
        for (int kk = 0; kk < 128; kk += 32) {
            __syncthreads();              // protect previous sB readers (also covers sA load on 1st iter)
            #pragma unroll
            for (int i = 0; i < 4; i++) {
                int id = i * 256 + t;     // float4 index 0..1023
                int r = id >> 5, c4 = id & 31;
                reinterpret_cast<float4*>(sB)[id] =
                    reinterpret_cast<const float4*>(We)[(kk + r) * 32 + c4];
            }
            __syncthreads();
            #pragma unroll
            for (int k = 0; k < 32; k++) {
                float av[4];
                #pragma unroll
                for (int i = 0; i < 4; i++) av[i] = sA[(ty * 4 + i) * 128 + kk + k];
                float4 b0 = reinterpret_cast<float4*>(sB)[k * 32 + tx * 2];
                float4 b1 = reinterpret_cast<float4*>(sB)[k * 32 + tx * 2 + 1];
                float bv[8] = {b0.x, b0.y, b0.z, b0.w, b1.x, b1.y, b1.z, b1.w};
                #pragma unroll
                for (int i = 0; i < 4; i++)
                    #pragma unroll
                    for (int j = 0; j < 8; j++)
                        acc[i][j] = fmaf(av[i], bv[j], acc[i][j]);
            }
        }
        // epilogue: gated relu accumulate
        #pragma unroll
        for (int i = 0; i < 4; i++) {
            int gr = row0 + ty * 4 + i;
            if (gr < n) {
                float gv = gate[gr * 3 + e];
                #pragma unroll
                for (int j = 0; j < 8; j++) {
                    float v = acc[i][j] + bias[e * 128 + cb + j];
                    v = fmaxf(v, 0.f);
                    o[i][j] = fmaf(gv, v, o[i][j]);
                }
            }
        }
    }
    #pragma unroll
    for (int i = 0; i < 4; i++) {
        int gr = row0 + ty * 4 + i;
        if (gr < n) {
            reinterpret_cast<float4*>(out + (long long)gr * 128 + cb)[0] =
                make_float4(o[i][0], o[i][1], o[i][2], o[i][3]);
            reinterpret_cast<float4*>(out + (long long)gr * 128 + cb)[1] =
                make_float4(o[i][4], o[i][5], o[i][6], o[i][7]);
        }
    }
}

__global__ void pool_zero_kernel() {
    int i = blockIdx.x * blockDim.x + threadIdx.x;
    int total = POOL_SPLITS * GG * FD;
    if (i < total) ((float*)g_pool)[i] = 0.f;
    else if (i < total + GG) g_cnt[i - total] = 0.f;
}

// one warp per node; red.v4 into split pool buffers
__global__ void pool_kernel(const float* __restrict__ h, const void* batch, int n) {
    int w = (blockIdx.x * blockDim.x + threadIdx.x) >> 5;
    int lane = threadIdx.x & 31;
    if (w >= n) return;
    int g = load_idx(batch, w);
    int slot = blockIdx.x & (POOL_SPLITS - 1);
    float4 v = reinterpret_cast<const float4*>(h)[(long long)w * 32 + lane];
    red_add_v4(&g_pool[slot][g * 128 + lane * 4], v);
    if (lane == 0) atomicAdd(&g_cnt[g], 1.0f);
}

// out[g,:] = (pool[g,:]/cnt[g]) @ Wf + bf   (tiny: 64x128x64)
__global__ void final_kernel(const float* __restrict__ Wf,
                             const float* __restrict__ bf,
                             float* __restrict__ outp) {
    __shared__ float sp[128];
    int gid = blockIdx.x;
    int t = threadIdx.x;   // 128 threads
    float s = 0.f;
    #pragma unroll
    for (int k = 0; k < POOL_SPLITS; k++) s += g_pool[k][gid * 128 + t];
    float c = fmaxf(g_cnt[gid], 1.0f);
    sp[t] = s / c;
    __syncthreads();
    if (t < OUTD) {
        float acc = bf[t];
        #pragma unroll
        for (int k = 0; k < 128; k++) acc = fmaf(sp[k], Wf[k * OUTD + t], acc);
        outp[gid * OUTD + t] = acc;
    }
}

// ---------------- launcher ----------------
extern "C" void kernel_launch(void* const* d_in, const int* in_sizes, int n_in,
                              void* d_out, int out_size) {
    const float* x    = (const float*)d_in[0];
    const float* top  = (const float*)d_in[1];
    const void*  ei   = d_in[2];
    const void*  batch= d_in[3];
    const float* W0   = (const float*)d_in[4];
    const float* b0   = (const float*)d_in[5];
    const float* Wg0  = (const float*)d_in[6];
    const float* W1   = (const float*)d_in[7];
    const float* b1   = (const float*)d_in[8];
    const float* Wg1  = (const float*)d_in[9];
    const float* Wf   = (const float*)d_in[10];
    const float* bf   = (const float*)d_in[11];
    float* out = (float*)d_out;

    const int N = in_sizes[0] / FD;
    const int E = in_sizes[2] / 2;

    // IMPORTANT: every __device__ symbol passed as a kernel argument must go
    // through cudaGetSymbolAddress. Host-side symbol names are host shadow
    // addresses; on GB300 (ATS) device reads of those silently return host
    // memory (zeros) instead of faulting. That was the R1 bug.
    float* bufA;  cudaGetSymbolAddress((void**)&bufA,  g_bufA);
    float* bufB;  cudaGetSymbolAddress((void**)&bufB,  g_bufB);
    float* gate0; cudaGetSymbolAddress((void**)&gate0, g_gate0);
    float* gate1; cudaGetSymbolAddress((void**)&gate1, g_gate1);

    const int TPB = 256;
    int nb_n   = (N + TPB - 1) / TPB;
    int nb_e   = (E + TPB - 1) / TPB;
    int nb_nf4 = (N * 32 + TPB - 1) / TPB;
    int nb_ew  = (E * 32 + TPB - 1) / TPB;   // warp per edge
    int nb_pw  = (N * 32 + TPB - 1) / TPB;   // warp per node
    int nb_moe = (N + 63) / 64;

    detect_kernel<<<1, 32>>>((const int*)ei);
    deg_init_kernel<<<nb_n, TPB>>>(N);
    deg_count_kernel<<<nb_e, TPB>>>(ei, E);
    deg_finish_kernel<<<nb_n, TPB>>>(N);
    gates_kernel<<<nb_n, TPB>>>(top, Wg0, Wg1, N);

    // layer 0: ah = A_norm @ x ; h1 = moe(ah)
    self_init_kernel<<<nb_nf4, TPB>>>(x, bufA, N);
    edge_agg_kernel<<<nb_ew, TPB>>>(x, bufA, ei, E);
    moe_kernel<<<nb_moe, TPB>>>(bufA, W0, b0, gate0, bufB, N);

    // layer 1: ah = A_norm @ h1 ; h2 = moe(ah)
    self_init_kernel<<<nb_nf4, TPB>>>(bufB, bufA, N);
    edge_agg_kernel<<<nb_ew, TPB>>>(bufB, bufA, ei, E);
    moe_kernel<<<nb_moe, TPB>>>(bufA, W1, b1, gate1, bufB, N);

    // pooling + final projection
    int total_pz = POOL_SPLITS * GG * FD + GG;
    pool_zero_kernel<<<(total_pz + TPB - 1) / TPB, TPB>>>();
    pool_kernel<<<nb_pw, TPB>>>(bufB, batch, N);
    final_kernel<<<GG, 128>>>(Wf, bf, out);
}

// round 5
// speedup vs baseline: 1.7751x; 1.7751x over previous
#include <cuda_runtime.h>
#include <cuda_bf16.h>
#include <cstdint>

// Problem constants (from reference)
#define NN      50000
#define EE      800000
#define FD      128
#define GG      64
#define OUTD    64
#define NEXP    3
#define TEMP_F  101.0f
#define POOL_SPLITS 16

// HMMA MoE config: padded bf16 images, 128 rows x 136 cols (stride 272B)
#define IMG_ELEMS 17408            // 128*136
#define IMG_B     34816            // bytes per image
#define ROWSTRIDE 272              // bytes per row
#define MOE_SMEM  (6 * IMG_B + 1536)   // Ah Al | Bbuf0(hi,lo) Bbuf1(hi,lo) | bias[384]

// ---------------- device scratch (no cudaMalloc allowed) ----------------
__device__ float g_dinv[NN];
__device__ float g_gate0[NN * NEXP];
__device__ float g_gate1[NN * NEXP];
__device__ float g_bufA[NN * FD];
__device__ float g_bufB[NN * FD];
__device__ float g_pool[POOL_SPLITS][GG * FD];
__device__ float g_cnt[GG];
__device__ int   g_is64;
// Pre-split weights: [layer(2)][expert(3)][hi,lo][128*136] bf16 (padded row-major [n][k])
__device__ __nv_bfloat16 g_wprep[2 * 3 * 2 * IMG_ELEMS];

// ---------------- helpers ----------------
__device__ __forceinline__ uint32_t smem_u32(const void* p) {
    uint32_t a;
    asm("{ .reg .u64 t; cvta.to.shared.u64 t, %1; cvt.u32.u64 %0, t; }" : "=r"(a) : "l"(p));
    return a;
}
__device__ __forceinline__ int load_idx(const void* p, long long i) {
    if (g_is64) return (int)((const long long*)p)[i];
    return ((const int*)p)[i];
}
__device__ __forceinline__ void red_add_v4(float* p, float4 v) {
    asm volatile("red.global.add.v4.f32 [%0], {%1,%2,%3,%4};"
                 :: "l"(p), "f"(v.x), "f"(v.y), "f"(v.z), "f"(v.w) : "memory");
}
__device__ __forceinline__ void cpa16(uint32_t dst, const void* src) {
    asm volatile("cp.async.cg.shared.global [%0], [%1], 16;" :: "r"(dst), "l"(src) : "memory");
}
#define CP_COMMIT() asm volatile("cp.async.commit_group;" ::: "memory")
#define CP_WAIT0()  asm volatile("cp.async.wait_group 0;" ::: "memory")

__device__ __forceinline__ void ldsm_x4(uint32_t (&r)[4], uint32_t addr) {
    asm volatile("ldmatrix.sync.aligned.m8n8.x4.shared.b16 {%0,%1,%2,%3}, [%4];"
                 : "=r"(r[0]), "=r"(r[1]), "=r"(r[2]), "=r"(r[3]) : "r"(addr));
}
__device__ __forceinline__ void ldsm_x2(uint32_t (&r)[2], uint32_t addr) {
    asm volatile("ldmatrix.sync.aligned.m8n8.x2.shared.b16 {%0,%1}, [%2];"
                 : "=r"(r[0]), "=r"(r[1]) : "r"(addr));
}
__device__ __forceinline__ void mma_bf16(float (&c)[4], const uint32_t (&a)[4],
                                         const uint32_t (&b)[2]) {
    asm volatile("mma.sync.aligned.m16n8k16.row.col.f32.bf16.bf16.f32 "
                 "{%0,%1,%2,%3}, {%4,%5,%6,%7}, {%8,%9}, {%0,%1,%2,%3};"
                 : "+f"(c[0]), "+f"(c[1]), "+f"(c[2]), "+f"(c[3])
                 : "r"(a[0]), "r"(a[1]), "r"(a[2]), "r"(a[3]), "r"(b[0]), "r"(b[1]));
}

// ---------------- small kernels ----------------
__global__ void detect_kernel(const int* p) {
    if (threadIdx.x == 0 && blockIdx.x == 0) {
        int all0 = 1;
        #pragma unroll
        for (int i = 1; i < 128; i += 2) if (p[i] != 0) all0 = 0;
        g_is64 = all0;
    }
}
__global__ void deg_init_kernel(int n) {
    int i = blockIdx.x * blockDim.x + threadIdx.x;
    if (i < n) g_dinv[i] = 1.0f;
}
__global__ void deg_count_kernel(const void* ei, int E) {
    int i = blockIdx.x * blockDim.x + threadIdx.x;
    if (i >= E) return;
    atomicAdd(&g_dinv[load_idx(ei, (long long)E + i)], 1.0f);
}
__global__ void deg_finish_kernel(int n) {
    int i = blockIdx.x * blockDim.x + threadIdx.x;
    if (i < n) g_dinv[i] = rsqrtf(g_dinv[i]);
}

__global__ void gates_kernel(const float* __restrict__ top,
                             const float* __restrict__ Wg0,
                             const float* __restrict__ Wg1, int n) {
    int i = blockIdx.x * blockDim.x + threadIdx.x;
    if (i >= n) return;
    float t0 = top[i * 4 + 0], t1 = top[i * 4 + 1];
    float t2 = top[i * 4 + 2], t3 = top[i * 4 + 3];
    const float* wgs[2] = {Wg0, Wg1};
    float* outs[2] = {g_gate0, g_gate1};
    #pragma unroll
    for (int L = 0; L < 2; L++) {
        const float* Wg = wgs[L];
        float l[NEXP];
        #pragma unroll
        for (int e = 0; e < NEXP; e++)
            l[e] = (t0 * Wg[e * 4 + 0] + t1 * Wg[e * 4 + 1] +
                    t2 * Wg[e * 4 + 2] + t3 * Wg[e * 4 + 3]) * (1.0f / TEMP_F);
        float m = fmaxf(l[0], fmaxf(l[1], l[2]));
        float e0 = __expf(l[0] - m), e1 = __expf(l[1] - m), e2 = __expf(l[2] - m);
        float inv = 1.0f / (e0 + e1 + e2);
        outs[L][i * 3 + 0] = e0 * inv;
        outs[L][i * 3 + 1] = e1 * inv;
        outs[L][i * 3 + 2] = e2 * inv;
    }
}

// Pre-split + transpose weights. block b = L*3+e. dst[n][k] = W[k][n], hi/lo bf16.
__global__ void wprep_kernel(const float* __restrict__ W0, const float* __restrict__ W1) {
    int b = blockIdx.x;
    const float* src = (b < 3 ? W0 : W1) + (b % 3) * (FD * FD);
    __nv_bfloat16* dhi = g_wprep + (size_t)b * 2 * IMG_ELEMS;
    __nv_bfloat16* dlo = dhi + IMG_ELEMS;
    for (int i = threadIdx.x; i < FD * FD; i += blockDim.x) {
        int nidx = i >> 7, k = i & 127;
        float v = src[k * FD + nidx];
        __nv_bfloat16 h = __float2bfloat16(v);
        __nv_bfloat16 l = __float2bfloat16(v - __bfloat162float(h));
        dhi[nidx * 136 + k] = h;
        dlo[nidx * 136 + k] = l;
    }
}

// out = dinv^2 * h  (layer-0 aggregation init from x)
__global__ void self_init_kernel(const float* __restrict__ h,
                                 float* __restrict__ outv, int n) {
    int id = blockIdx.x * blockDim.x + threadIdx.x;
    if (id >= n * 32) return;
    int node = id >> 5;
    float s = g_dinv[node]; s = s * s;
    float4 v = reinterpret_cast<const float4*>(h)[id];
    v.x *= s; v.y *= s; v.z *= s; v.w *= s;
    reinterpret_cast<float4*>(outv)[id] = v;
}

// out[dst] += dinv[src]*dinv[dst]*h[src]  -- one warp per edge
__global__ void edge_agg_kernel(const float* __restrict__ h,
                                float* __restrict__ outv,
                                const void* __restrict__ ei, int E) {
    int w = (blockIdx.x * blockDim.x + threadIdx.x) >> 5;
    int lane = threadIdx.x & 31;
    if (w >= E) return;
    int s = load_idx(ei, w);
    int d = load_idx(ei, (long long)E + w);
    float nrm = g_dinv[s] * g_dinv[d];
    float4 v = reinterpret_cast<const float4*>(h)[(long long)s * 32 + lane];
    v.x *= nrm; v.y *= nrm; v.z *= nrm; v.w *= nrm;
    red_add_v4(outv + (long long)d * 128 + lane * 4, v);
}

// ---------------- HMMA MoE layer ----------------
// out[m,:] = sum_e gate[m,e]*relu(A[m,:] @ W_e + b_e), bf16 hi/lo 3-term split.
// Virtual K=384 per expert: [Ah|Al|Ah] x [Bh|Bh|Bl]. Warp tile 32x64 (m16n8k16).
__global__ void __launch_bounds__(256, 1)
moe_hmma_kernel(const float* __restrict__ A, const __nv_bfloat16* __restrict__ wprepL,
                const float* __restrict__ bias, const float* __restrict__ gate,
                float* __restrict__ out, float* __restrict__ selfout, int n)
{
    extern __shared__ char smem[];
    const uint32_t sb = smem_u32(smem);
    const int t = threadIdx.x, lane = t & 31, wid = t >> 5;
    const int row0 = blockIdx.x * 128;
    float* sBias = (float*)(smem + 6 * IMG_B);

    for (int i = t; i < NEXP * FD; i += 256) sBias[i] = bias[i];

    // A tile: fp32 -> bf16 hi/lo split into padded images Ah@0, Al@IMG_B
    #pragma unroll
    for (int i = 0; i < 16; i++) {
        int id = i * 256 + t;
        int r = id >> 5, c4 = id & 31, k0 = c4 * 4;
        int gr = row0 + r;
        float4 v = make_float4(0.f, 0.f, 0.f, 0.f);
        if (gr < n) v = reinterpret_cast<const float4*>(A)[(size_t)gr * 32 + c4];
        float vv[4] = {v.x, v.y, v.z, v.w};
        __nv_bfloat16 h[4], l[4];
        #pragma unroll
        for (int j = 0; j < 4; j++) {
            h[j] = __float2bfloat16(vv[j]);
            l[j] = __float2bfloat16(vv[j] - __bfloat162float(h[j]));
        }
        *(uint64_t*)(smem + r * ROWSTRIDE + k0 * 2)         = *(const uint64_t*)h;
        *(uint64_t*)(smem + IMG_B + r * ROWSTRIDE + k0 * 2) = *(const uint64_t*)l;
    }

    // prefetch expert-0 B (hi+lo = 2 images contiguous) into buf0
    {
        uint32_t dst = sb + 2 * IMG_B;
        const char* src = (const char*)wprepL;
        for (int i = t; i < 2 * IMG_B / 16; i += 256) cpa16(dst + i * 16, src + i * 16);
        CP_COMMIT();
    }
    __syncthreads();
    CP_WAIT0();
    __syncthreads();

    const int m0 = (wid & 3) * 32, n0 = (wid >> 2) * 64;
    // ldmatrix per-thread offsets (bytes)
    uint32_t aoff[2];
    #pragma unroll
    for (int mt = 0; mt < 2; mt++)
        aoff[mt] = (uint32_t)((m0 + mt * 16 + (lane & 7) + ((lane >> 3) & 1) * 8) * ROWSTRIDE
                              + (lane >> 4) * 16);
    const int l16 = lane & 15;
    uint32_t boff[8];
    #pragma unroll
    for (int nt = 0; nt < 8; nt++)
        boff[nt] = (uint32_t)((n0 + nt * 8 + (l16 & 7)) * ROWSTRIDE + (l16 >> 3) * 16);

    float o[2][8][4];
    #pragma unroll
    for (int mt = 0; mt < 2; mt++)
        #pragma unroll
        for (int nt = 0; nt < 8; nt++)
            #pragma unroll
            for (int j = 0; j < 4; j++) o[mt][nt][j] = 0.f;

    for (int e = 0; e < NEXP; e++) {
        const uint32_t bbase = sb + 2 * IMG_B + (uint32_t)(e & 1) * 2 * IMG_B;
        if (e < 2) {   // prefetch next expert into the other buffer
            uint32_t dst = sb + 2 * IMG_B + (uint32_t)((e + 1) & 1) * 2 * IMG_B;
            const char* src = (const char*)(wprepL + (size_t)(e + 1) * 2 * IMG_ELEMS);
            for (int i = t; i < 2 * IMG_B / 16; i += 256) cpa16(dst + i * 16, src + i * 16);
            CP_COMMIT();
        }

        float c[2][8][4];
        #pragma unroll
        for (int mt = 0; mt < 2; mt++)
            #pragma unroll
            for (int nt = 0; nt < 8; nt++)
                #pragma unroll
                for (int j = 0; j < 4; j++) c[mt][nt][j] = 0.f;

        #pragma unroll 4
        for (int ks = 0; ks < 24; ks++) {
            int term = ks >> 3;
            uint32_t kb = (uint32_t)((ks & 7) * 32);           // 16 bf16 = 32B
            uint32_t abase = sb + (term == 1 ? IMG_B : 0u) + kb;
            uint32_t bbs   = bbase + (term == 2 ? IMG_B : 0u) + kb;
            uint32_t a[2][4], b[8][2];
            #pragma unroll
            for (int mt = 0; mt < 2; mt++) ldsm_x4(a[mt], abase + aoff[mt]);
            #pragma unroll
            for (int nt = 0; nt < 8; nt++) ldsm_x2(b[nt], bbs + boff[nt]);
            #pragma unroll
            for (int mt = 0; mt < 2; mt++)
                #pragma unroll
                for (int nt = 0; nt < 8; nt++) mma_bf16(c[mt][nt], a[mt], b[nt]);
        }

        // gated relu epilogue into o
        #pragma unroll
        for (int mt = 0; mt < 2; mt++) {
            int r0 = row0 + m0 + mt * 16 + (lane >> 2);
            int r1 = r0 + 8;
            float g0 = (r0 < n) ? gate[r0 * 3 + e] : 0.f;
            float g1 = (r1 < n) ? gate[r1 * 3 + e] : 0.f;
            #pragma unroll
            for (int nt = 0; nt < 8; nt++) {
                int nc = n0 + nt * 8 + 2 * (lane & 3);
                float b0v = sBias[e * 128 + nc], b1v = sBias[e * 128 + nc + 1];
                o[mt][nt][0] = fmaf(g0, fmaxf(c[mt][nt][0] + b0v, 0.f), o[mt][nt][0]);
                o[mt][nt][1] = fmaf(g0, fmaxf(c[mt][nt][1] + b1v, 0.f), o[mt][nt][1]);
                o[mt][nt][2] = fmaf(g1, fmaxf(c[mt][nt][2] + b0v, 0.f), o[mt][nt][2]);
                o[mt][nt][3] = fmaf(g1, fmaxf(c[mt][nt][3] + b1v, 0.f), o[mt][nt][3]);
            }
        }
        if (e < 2) CP_WAIT0();
        __syncthreads();
    }

    // store (+ fused dinv^2 copy for next layer's aggregation init)
    #pragma unroll
    for (int mt = 0; mt < 2; mt++) {
        int r0 = row0 + m0 + mt * 16 + (lane >> 2);
        int r1 = r0 + 8;
        float s0 = 0.f, s1 = 0.f;
        if (selfout) {
            if (r0 < n) { s0 = g_dinv[r0]; s0 *= s0; }
            if (r1 < n) { s1 = g_dinv[r1]; s1 *= s1; }
        }
        #pragma unroll
        for (int nt = 0; nt < 8; nt++) {
            int nc = n0 + nt * 8 + 2 * (lane & 3);
            if (r0 < n) {
                *(float2*)(out + (size_t)r0 * 128 + nc) = make_float2(o[mt][nt][0], o[mt][nt][1]);
                if (selfout)
                    *(float2*)(selfout + (size_t)r0 * 128 + nc) =
                        make_float2(s0 * o[mt][nt][0], s0 * o[mt][nt][1]);
            }
            if (r1 < n) {
                *(float2*)(out + (size_t)r1 * 128 + nc) = make_float2(o[mt][nt][2], o[mt][nt][3]);
                if (selfout)
                    *(float2*)(selfout + (size_t)r1 * 128 + nc) =
                        make_float2(s1 * o[mt][nt][2], s1 * o[mt][nt][3]);
            }
        }
    }
}

// ---------------- pooling + final ----------------
__global__ void pool_zero_kernel() {
    int i = blockIdx.x * blockDim.x + threadIdx.x;
    int total = POOL_SPLITS * GG * FD;
    if (i < total) ((float*)g_pool)[i] = 0.f;
    else if (i < total + GG) g_cnt[i - total] = 0.f;
}
__global__ void pool_kernel(const float* __restrict__ h, const void* batch, int n) {
    int w = (blockIdx.x * blockDim.x + threadIdx.x) >> 5;
    int lane = threadIdx.x & 31;
    if (w >= n) return;
    int g = load_idx(batch, w);
    int slot = blockIdx.x & (POOL_SPLITS - 1);
    float4 v = reinterpret_cast<const float4*>(h)[(long long)w * 32 + lane];
    red_add_v4(&g_pool[slot][g * 128 + lane * 4], v);
    if (lane == 0) atomicAdd(&g_cnt[g], 1.0f);
}
__global__ void final_kernel(const float* __restrict__ Wf,
                             const float* __restrict__ bf,
                             float* __restrict__ outp) {
    __shared__ float sp[128];
    int gid = blockIdx.x, t = threadIdx.x;
    float s = 0.f;
    #pragma unroll
    for (int k = 0; k < POOL_SPLITS; k++) s += g_pool[k][gid * 128 + t];
    sp[t] = s / fmaxf(g_cnt[gid], 1.0f);
    __syncthreads();
    if (t < OUTD) {
        float acc = bf[t];
        #pragma unroll
        for (int k = 0; k < 128; k++) acc = fmaf(sp[k], Wf[k * OUTD + t], acc);
        outp[gid * OUTD + t] = acc;
    }
}

// ---------------- launcher ----------------
extern "C" void kernel_launch(void* const* d_in, const int* in_sizes, int n_in,
                              void* d_out, int out_size) {
    const float* x    = (const float*)d_in[0];
    const float* top  = (const float*)d_in[1];
    const void*  ei   = d_in[2];
    const void*  batch= d_in[3];
    const float* W0   = (const float*)d_in[4];
    const float* b0   = (const float*)d_in[5];
    const float* Wg0  = (const float*)d_in[6];
    const float* W1   = (const float*)d_in[7];
    const float* b1   = (const float*)d_in[8];
    const float* Wg1  = (const float*)d_in[9];
    const float* Wf   = (const float*)d_in[10];
    const float* bf   = (const float*)d_in[11];
    float* out = (float*)d_out;

    const int N = in_sizes[0] / FD;
    const int E = in_sizes[2] / 2;

    // Device addresses for symbols passed as kernel args (R1 lesson).
    float* bufA;  cudaGetSymbolAddress((void**)&bufA,  g_bufA);
    float* bufB;  cudaGetSymbolAddress((void**)&bufB,  g_bufB);
    float* gate0; cudaGetSymbolAddress((void**)&gate0, g_gate0);
    float* gate1; cudaGetSymbolAddress((void**)&gate1, g_gate1);
    __nv_bfloat16* wprep; cudaGetSymbolAddress((void**)&wprep, g_wprep);

    cudaFuncSetAttribute(moe_hmma_kernel, cudaFuncAttributeMaxDynamicSharedMemorySize, MOE_SMEM);

    const int TPB = 256;
    int nb_n   = (N + TPB - 1) / TPB;
    int nb_e   = (E + TPB - 1) / TPB;
    int nb_nf4 = (N * 32 + TPB - 1) / TPB;
    int nb_ew  = (E * 32 + TPB - 1) / TPB;
    int nb_pw  = (N * 32 + TPB - 1) / TPB;
    int nb_moe = (N + 127) / 128;

    detect_kernel<<<1, 32>>>((const int*)ei);
    deg_init_kernel<<<nb_n, TPB>>>(N);
    deg_count_kernel<<<nb_e, TPB>>>(ei, E);
    deg_finish_kernel<<<nb_n, TPB>>>(N);
    gates_kernel<<<nb_n, TPB>>>(top, Wg0, Wg1, N);
    wprep_kernel<<<6, TPB>>>(W0, W1);

    // layer 0: bufA = A_norm @ x ; bufB = moe(bufA); bufA = dinv^2*bufB (fused)
    self_init_kernel<<<nb_nf4, TPB>>>(x, bufA, N);
    edge_agg_kernel<<<nb_ew, TPB>>>(x, bufA, ei, E);
    moe_hmma_kernel<<<nb_moe, TPB, MOE_SMEM>>>(bufA, wprep, b0, gate0, bufB, bufA, N);

    // layer 1: bufA += edges(bufB) ; bufB = moe(bufA)
    edge_agg_kernel<<<nb_ew, TPB>>>(bufB, bufA, ei, E);
    moe_hmma_kernel<<<nb_moe, TPB, MOE_SMEM>>>(bufA, wprep + 3 * 2 * IMG_ELEMS, b1, gate1,
                                               bufB, nullptr, N);

    // pooling + final projection
    int total_pz = POOL_SPLITS * GG * FD + GG;
    pool_zero_kernel<<<(total_pz + TPB - 1) / TPB, TPB>>>();
    pool_kernel<<<nb_pw, TPB>>>(bufB, batch, N);
    final_kernel<<<GG, 128>>>(Wf, bf, out);
}

// round 6
// speedup vs baseline: 2.3533x; 1.3257x over previous
#include <cuda_runtime.h>
#include <cuda_bf16.h>
#include <cstdint>

// Problem constants (from reference)
#define NN      50000
#define EE      800000
#define FD      128
#define GG      64
#define OUTD    64
#define NEXP    3
#define TEMP_F  101.0f

// HMMA MoE config: padded bf16 images, 128 rows x 136 cols (stride 272B)
#define IMG_ELEMS 17408            // 128*136
#define IMG_B     34816            // bytes per image
#define ROWSTRIDE 272              // bytes per row
#define MOE_SMEM  (6 * IMG_B + 1536)   // Ah Al | Bbuf0(hi,lo) Bbuf1(hi,lo) | bias[384]

// ---------------- device scratch (no cudaMalloc allowed) ----------------
__device__ float g_dinv[NN];
__device__ int   g_degE[NN];          // in-edge count (no self loop)
__device__ int   g_fill[NN];
__device__ int   g_off[NN + 1];       // CSR row offsets
__device__ int   g_csr[EE];           // CSR src indices
__device__ float g_gate0[NN * NEXP];
__device__ float g_gate1[NN * NEXP];
__device__ float g_bufA[NN * FD];
__device__ float g_bufB[NN * FD];
__device__ int   g_is64;
// Pre-split weights: [layer(2)][expert(3)][hi,lo][128*136] bf16 (padded row-major [n][k])
__device__ __nv_bfloat16 g_wprep[2 * 3 * 2 * IMG_ELEMS];

// ---------------- helpers ----------------
__device__ __forceinline__ uint32_t smem_u32(const void* p) {
    uint32_t a;
    asm("{ .reg .u64 t; cvta.to.shared.u64 t, %1; cvt.u32.u64 %0, t; }" : "=r"(a) : "l"(p));
    return a;
}
__device__ __forceinline__ int load_idx(const void* p, long long i) {
    if (g_is64) return (int)((const long long*)p)[i];
    return ((const int*)p)[i];
}
__device__ __forceinline__ void cpa16(uint32_t dst, const void* src) {
    asm volatile("cp.async.cg.shared.global [%0], [%1], 16;" :: "r"(dst), "l"(src) : "memory");
}
#define CP_COMMIT() asm volatile("cp.async.commit_group;" ::: "memory")
#define CP_WAIT0()  asm volatile("cp.async.wait_group 0;" ::: "memory")

__device__ __forceinline__ void ldsm_x4(uint32_t (&r)[4], uint32_t addr) {
    asm volatile("ldmatrix.sync.aligned.m8n8.x4.shared.b16 {%0,%1,%2,%3}, [%4];"
                 : "=r"(r[0]), "=r"(r[1]), "=r"(r[2]), "=r"(r[3]) : "r"(addr));
}
__device__ __forceinline__ void ldsm_x2(uint32_t (&r)[2], uint32_t addr) {
    asm volatile("ldmatrix.sync.aligned.m8n8.x2.shared.b16 {%0,%1}, [%2];"
                 : "=r"(r[0]), "=r"(r[1]) : "r"(addr));
}
__device__ __forceinline__ void mma_bf16(float (&c)[4], const uint32_t (&a)[4],
                                         const uint32_t (&b)[2]) {
    asm volatile("mma.sync.aligned.m16n8k16.row.col.f32.bf16.bf16.f32 "
                 "{%0,%1,%2,%3}, {%4,%5,%6,%7}, {%8,%9}, {%0,%1,%2,%3};"
                 : "+f"(c[0]), "+f"(c[1]), "+f"(c[2]), "+f"(c[3])
                 : "r"(a[0]), "r"(a[1]), "r"(a[2]), "r"(a[3]), "r"(b[0]), "r"(b[1]));
}

// ---------------- graph-prep kernels ----------------
__global__ void detect_kernel(const int* p) {
    if (threadIdx.x == 0 && blockIdx.x == 0) {
        int all0 = 1;
        #pragma unroll
        for (int i = 1; i < 128; i += 2) if (p[i] != 0) all0 = 0;
        g_is64 = all0;
    }
}
__global__ void deg_init_kernel(int n) {
    int i = blockIdx.x * blockDim.x + threadIdx.x;
    if (i < n) { g_degE[i] = 0; g_fill[i] = 0; }
}
__global__ void deg_count_kernel(const void* ei, int E) {
    int i = blockIdx.x * blockDim.x + threadIdx.x;
    if (i >= E) return;
    atomicAdd(&g_degE[load_idx(ei, (long long)E + i)], 1);
}

// Single-block exclusive scan of g_degE into g_off (n <= 50176)
__global__ void __launch_bounds__(1024, 1) scan_kernel(int n) {
    __shared__ int ssum[1024];
    const int t = threadIdx.x;
    const int C = (n + 1023) >> 10;
    const int lo = t * C, hi = min(n, lo + C);
    int local = 0;
    for (int i = lo; i < hi; i++) local += g_degE[i];
    ssum[t] = local;
    __syncthreads();
    // Hillis-Steele inclusive scan
    for (int off = 1; off < 1024; off <<= 1) {
        int v = (t >= off) ? ssum[t - off] : 0;
        __syncthreads();
        ssum[t] += v;
        __syncthreads();
    }
    int run = ssum[t] - local;   // exclusive prefix for this chunk
    for (int i = lo; i < hi; i++) { g_off[i] = run; run += g_degE[i]; }
    if (t == 1023) g_off[n] = ssum[1023];
}

__global__ void scatter_kernel(const void* ei, int E) {
    int i = blockIdx.x * blockDim.x + threadIdx.x;
    if (i >= E) return;
    int s = load_idx(ei, i);
    int d = load_idx(ei, (long long)E + i);
    int pos = g_off[d] + atomicAdd(&g_fill[d], 1);
    g_csr[pos] = s;
}

// dinv + both layers' gates (fused per-node prep)
__global__ void node_prep_kernel(const float* __restrict__ top,
                                 const float* __restrict__ Wg0,
                                 const float* __restrict__ Wg1, int n) {
    int i = blockIdx.x * blockDim.x + threadIdx.x;
    if (i >= n) return;
    g_dinv[i] = rsqrtf((float)(g_degE[i] + 1));
    float t0 = top[i * 4 + 0], t1 = top[i * 4 + 1];
    float t2 = top[i * 4 + 2], t3 = top[i * 4 + 3];
    const float* wgs[2] = {Wg0, Wg1};
    float* outs[2] = {g_gate0, g_gate1};
    #pragma unroll
    for (int L = 0; L < 2; L++) {
        const float* Wg = wgs[L];
        float l[NEXP];
        #pragma unroll
        for (int e = 0; e < NEXP; e++)
            l[e] = (t0 * Wg[e * 4 + 0] + t1 * Wg[e * 4 + 1] +
                    t2 * Wg[e * 4 + 2] + t3 * Wg[e * 4 + 3]) * (1.0f / TEMP_F);
        float m = fmaxf(l[0], fmaxf(l[1], l[2]));
        float e0 = __expf(l[0] - m), e1 = __expf(l[1] - m), e2 = __expf(l[2] - m);
        float inv = 1.0f / (e0 + e1 + e2);
        outs[L][i * 3 + 0] = e0 * inv;
        outs[L][i * 3 + 1] = e1 * inv;
        outs[L][i * 3 + 2] = e2 * inv;
    }
}

// Pre-split + transpose weights. block b = L*3+e. dst[n][k] = W[k][n], hi/lo bf16.
__global__ void wprep_kernel(const float* __restrict__ W0, const float* __restrict__ W1) {
    int b = blockIdx.x;
    const float* src = (b < 3 ? W0 : W1) + (b % 3) * (FD * FD);
    __nv_bfloat16* dhi = g_wprep + (size_t)b * 2 * IMG_ELEMS;
    __nv_bfloat16* dlo = dhi + IMG_ELEMS;
    for (int i = threadIdx.x; i < FD * FD; i += blockDim.x) {
        int nidx = i >> 7, k = i & 127;
        float v = src[k * FD + nidx];
        __nv_bfloat16 h = __float2bfloat16(v);
        __nv_bfloat16 l = __float2bfloat16(v - __bfloat162float(h));
        dhi[nidx * 136 + k] = h;
        dlo[nidx * 136 + k] = l;
    }
}

// ---------------- CSR aggregation: pure gather, no atomics ----------------
// out[r,:] = dinv[r]^2*h[r,:] + sum_{e in row r} dinv[r]*dinv[src]*h[src,:]
// One warp per row; lane owns one float4 slice.
__global__ void agg_csr_kernel(const float* __restrict__ h,
                               float* __restrict__ out, int n) {
    int r = (blockIdx.x * blockDim.x + threadIdx.x) >> 5;
    int lane = threadIdx.x & 31;
    if (r >= n) return;
    const float4* hp = (const float4*)h;
    float di = g_dinv[r];
    float4 self = hp[(size_t)r * 32 + lane];
    float s2 = di * di;
    float4 acc = make_float4(s2 * self.x, s2 * self.y, s2 * self.z, s2 * self.w);
    int e = g_off[r], e1 = g_off[r + 1];
    for (; e + 2 <= e1; e += 2) {
        int s0 = g_csr[e], s1 = g_csr[e + 1];
        float n0 = di * g_dinv[s0], n1 = di * g_dinv[s1];
        float4 v0 = hp[(size_t)s0 * 32 + lane];
        float4 v1 = hp[(size_t)s1 * 32 + lane];
        acc.x = fmaf(n0, v0.x, fmaf(n1, v1.x, acc.x));
        acc.y = fmaf(n0, v0.y, fmaf(n1, v1.y, acc.y));
        acc.z = fmaf(n0, v0.z, fmaf(n1, v1.z, acc.z));
        acc.w = fmaf(n0, v0.w, fmaf(n1, v1.w, acc.w));
    }
    if (e < e1) {
        int s0 = g_csr[e];
        float n0 = di * g_dinv[s0];
        float4 v0 = hp[(size_t)s0 * 32 + lane];
        acc.x = fmaf(n0, v0.x, acc.x);
        acc.y = fmaf(n0, v0.y, acc.y);
        acc.z = fmaf(n0, v0.z, acc.z);
        acc.w = fmaf(n0, v0.w, acc.w);
    }
    ((float4*)out)[(size_t)r * 32 + lane] = acc;
}

// ---------------- HMMA MoE layer ----------------
// out[m,:] = sum_e gate[m,e]*relu(A[m,:] @ W_e + b_e), bf16 hi/lo 3-term split.
__global__ void __launch_bounds__(256, 1)
moe_hmma_kernel(const float* __restrict__ A, const __nv_bfloat16* __restrict__ wprepL,
                const float* __restrict__ bias, const float* __restrict__ gate,
                float* __restrict__ out, int n)
{
    extern __shared__ char smem[];
    const uint32_t sb = smem_u32(smem);
    const int t = threadIdx.x, lane = t & 31, wid = t >> 5;
    const int row0 = blockIdx.x * 128;
    float* sBias = (float*)(smem + 6 * IMG_B);

    for (int i = t; i < NEXP * FD; i += 256) sBias[i] = bias[i];

    // A tile: fp32 -> bf16 hi/lo split into padded images Ah@0, Al@IMG_B
    #pragma unroll
    for (int i = 0; i < 16; i++) {
        int id = i * 256 + t;
        int r = id >> 5, c4 = id & 31, k0 = c4 * 4;
        int gr = row0 + r;
        float4 v = make_float4(0.f, 0.f, 0.f, 0.f);
        if (gr < n) v = reinterpret_cast<const float4*>(A)[(size_t)gr * 32 + c4];
        float vv[4] = {v.x, v.y, v.z, v.w};
        __nv_bfloat16 h[4], l[4];
        #pragma unroll
        for (int j = 0; j < 4; j++) {
            h[j] = __float2bfloat16(vv[j]);
            l[j] = __float2bfloat16(vv[j] - __bfloat162float(h[j]));
        }
        *(uint64_t*)(smem + r * ROWSTRIDE + k0 * 2)         = *(const uint64_t*)h;
        *(uint64_t*)(smem + IMG_B + r * ROWSTRIDE + k0 * 2) = *(const uint64_t*)l;
    }

    // prefetch expert-0 B (hi+lo contiguous) into buf0
    {
        uint32_t dst = sb + 2 * IMG_B;
        const char* src = (const char*)wprepL;
        for (int i = t; i < 2 * IMG_B / 16; i += 256) cpa16(dst + i * 16, src + i * 16);
        CP_COMMIT();
    }
    __syncthreads();
    CP_WAIT0();
    __syncthreads();

    const int m0 = (wid & 3) * 32, n0 = (wid >> 2) * 64;
    uint32_t aoff[2];
    #pragma unroll
    for (int mt = 0; mt < 2; mt++)
        aoff[mt] = (uint32_t)((m0 + mt * 16 + (lane & 7) + ((lane >> 3) & 1) * 8) * ROWSTRIDE
                              + (lane >> 4) * 16);
    const int l16 = lane & 15;
    uint32_t boff[8];
    #pragma unroll
    for (int nt = 0; nt < 8; nt++)
        boff[nt] = (uint32_t)((n0 + nt * 8 + (l16 & 7)) * ROWSTRIDE + (l16 >> 3) * 16);

    float o[2][8][4];
    #pragma unroll
    for (int mt = 0; mt < 2; mt++)
        #pragma unroll
        for (int nt = 0; nt < 8; nt++)
            #pragma unroll
            for (int j = 0; j < 4; j++) o[mt][nt][j] = 0.f;

    for (int e = 0; e < NEXP; e++) {
        const uint32_t bbase = sb + 2 * IMG_B + (uint32_t)(e & 1) * 2 * IMG_B;
        if (e < 2) {
            uint32_t dst = sb + 2 * IMG_B + (uint32_t)((e + 1) & 1) * 2 * IMG_B;
            const char* src = (const char*)(wprepL + (size_t)(e + 1) * 2 * IMG_ELEMS);
            for (int i = t; i < 2 * IMG_B / 16; i += 256) cpa16(dst + i * 16, src + i * 16);
            CP_COMMIT();
        }

        float c[2][8][4];
        #pragma unroll
        for (int mt = 0; mt < 2; mt++)
            #pragma unroll
            for (int nt = 0; nt < 8; nt++)
                #pragma unroll
                for (int j = 0; j < 4; j++) c[mt][nt][j] = 0.f;

        #pragma unroll 4
        for (int ks = 0; ks < 24; ks++) {
            int term = ks >> 3;
            uint32_t kb = (uint32_t)((ks & 7) * 32);
            uint32_t abase = sb + (term == 1 ? IMG_B : 0u) + kb;
            uint32_t bbs   = bbase + (term == 2 ? IMG_B : 0u) + kb;
            uint32_t a[2][4], b[8][2];
            #pragma unroll
            for (int mt = 0; mt < 2; mt++) ldsm_x4(a[mt], abase + aoff[mt]);
            #pragma unroll
            for (int nt = 0; nt < 8; nt++) ldsm_x2(b[nt], bbs + boff[nt]);
            #pragma unroll
            for (int mt = 0; mt < 2; mt++)
                #pragma unroll
                for (int nt = 0; nt < 8; nt++) mma_bf16(c[mt][nt], a[mt], b[nt]);
        }

        #pragma unroll
        for (int mt = 0; mt < 2; mt++) {
            int r0 = row0 + m0 + mt * 16 + (lane >> 2);
            int r1 = r0 + 8;
            float g0 = (r0 < n) ? gate[r0 * 3 + e] : 0.f;
            float g1 = (r1 < n) ? gate[r1 * 3 + e] : 0.f;
            #pragma unroll
            for (int nt = 0; nt < 8; nt++) {
                int nc = n0 + nt * 8 + 2 * (lane & 3);
                float b0v = sBias[e * 128 + nc], b1v = sBias[e * 128 + nc + 1];
                o[mt][nt][0] = fmaf(g0, fmaxf(c[mt][nt][0] + b0v, 0.f), o[mt][nt][0]);
                o[mt][nt][1] = fmaf(g0, fmaxf(c[mt][nt][1] + b1v, 0.f), o[mt][nt][1]);
                o[mt][nt][2] = fmaf(g1, fmaxf(c[mt][nt][2] + b0v, 0.f), o[mt][nt][2]);
                o[mt][nt][3] = fmaf(g1, fmaxf(c[mt][nt][3] + b1v, 0.f), o[mt][nt][3]);
            }
        }
        if (e < 2) CP_WAIT0();
        __syncthreads();
    }

    #pragma unroll
    for (int mt = 0; mt < 2; mt++) {
        int r0 = row0 + m0 + mt * 16 + (lane >> 2);
        int r1 = r0 + 8;
        #pragma unroll
        for (int nt = 0; nt < 8; nt++) {
            int nc = n0 + nt * 8 + 2 * (lane & 3);
            if (r0 < n)
                *(float2*)(out + (size_t)r0 * 128 + nc) = make_float2(o[mt][nt][0], o[mt][nt][1]);
            if (r1 < n)
                *(float2*)(out + (size_t)r1 * 128 + nc) = make_float2(o[mt][nt][2], o[mt][nt][3]);
        }
    }
}

// ---------------- fused pool + final (batch is sorted) ----------------
__device__ __forceinline__ int lbound_batch(const void* b, int n, long long key) {
    int lo = 0, hi = n;
    while (lo < hi) {
        int m = (lo + hi) >> 1;
        long long v = g_is64 ? ((const long long*)b)[m] : (long long)((const int*)b)[m];
        if (v < key) lo = m + 1; else hi = m;
    }
    return lo;
}

__global__ void pool_final_kernel(const float* __restrict__ h, const void* batch,
                                  const float* __restrict__ Wf,
                                  const float* __restrict__ bf,
                                  float* __restrict__ outp, int n) {
    __shared__ float sp[128];
    __shared__ int sLo, sHi;
    const int g = blockIdx.x, t = threadIdx.x;
    if (t == 0) sLo = lbound_batch(batch, n, g);
    if (t == 1) sHi = lbound_batch(batch, n, g + 1);
    __syncthreads();
    const int lo = sLo, hi = sHi;
    float s = 0.f;
    int r = lo;
    for (; r + 4 <= hi; r += 4) {
        s += h[(size_t)r * 128 + t] + h[(size_t)(r + 1) * 128 + t] +
             h[(size_t)(r + 2) * 128 + t] + h[(size_t)(r + 3) * 128 + t];
    }
    for (; r < hi; r++) s += h[(size_t)r * 128 + t];
    sp[t] = s / fmaxf((float)(hi - lo), 1.0f);
    __syncthreads();
    if (t < OUTD) {
        float acc = bf[t];
        #pragma unroll
        for (int k = 0; k < 128; k++) acc = fmaf(sp[k], Wf[k * OUTD + t], acc);
        outp[g * OUTD + t] = acc;
    }
}

// ---------------- launcher ----------------
extern "C" void kernel_launch(void* const* d_in, const int* in_sizes, int n_in,
                              void* d_out, int out_size) {
    const float* x    = (const float*)d_in[0];
    const float* top  = (const float*)d_in[1];
    const void*  ei   = d_in[2];
    const void*  batch= d_in[3];
    const float* W0   = (const float*)d_in[4];
    const float* b0   = (const float*)d_in[5];
    const float* Wg0  = (const float*)d_in[6];
    const float* W1   = (const float*)d_in[7];
    const float* b1   = (const float*)d_in[8];
    const float* Wg1  = (const float*)d_in[9];
    const float* Wf   = (const float*)d_in[10];
    const float* bf   = (const float*)d_in[11];
    float* out = (float*)d_out;

    const int N = in_sizes[0] / FD;
    const int E = in_sizes[2] / 2;

    // Device addresses for symbols passed as kernel args (R1 lesson: ATS makes
    // host-shadow symbol reads silently return host zeros).
    float* bufA;  cudaGetSymbolAddress((void**)&bufA,  g_bufA);
    float* bufB;  cudaGetSymbolAddress((void**)&bufB,  g_bufB);
    float* gate0; cudaGetSymbolAddress((void**)&gate0, g_gate0);
    float* gate1; cudaGetSymbolAddress((void**)&gate1, g_gate1);
    __nv_bfloat16* wprep; cudaGetSymbolAddress((void**)&wprep, g_wprep);

    cudaFuncSetAttribute(moe_hmma_kernel, cudaFuncAttributeMaxDynamicSharedMemorySize, MOE_SMEM);

    const int TPB = 256;
    int nb_n   = (N + TPB - 1) / TPB;
    int nb_e   = (E + TPB - 1) / TPB;
    int nb_aw  = (N * 32 + TPB - 1) / TPB;   // warp per row
    int nb_moe = (N + 127) / 128;

    // graph prep: degrees -> CSR -> dinv/gates
    detect_kernel<<<1, 32>>>((const int*)ei);
    deg_init_kernel<<<nb_n, TPB>>>(N);
    deg_count_kernel<<<nb_e, TPB>>>(ei, E);
    scan_kernel<<<1, 1024>>>(N);
    scatter_kernel<<<nb_e, TPB>>>(ei, E);
    node_prep_kernel<<<nb_n, TPB>>>(top, Wg0, Wg1, N);
    wprep_kernel<<<6, TPB>>>(W0, W1);

    // layer 0
    agg_csr_kernel<<<nb_aw, TPB>>>(x, bufA, N);
    moe_hmma_kernel<<<nb_moe, TPB, MOE_SMEM>>>(bufA, wprep, b0, gate0, bufB, N);
    // layer 1
    agg_csr_kernel<<<nb_aw, TPB>>>(bufB, bufA, N);
    moe_hmma_kernel<<<nb_moe, TPB, MOE_SMEM>>>(bufA, wprep + 3 * 2 * IMG_ELEMS, b1, gate1, bufB, N);

    // fused pooling + final projection
    pool_final_kernel<<<GG, 128>>>(bufB, batch, Wf, bf, out, N);
}

// round 7
// speedup vs baseline: 2.7572x; 1.1717x over previous
#include <cuda_runtime.h>
#include <cuda_bf16.h>
#include <cstdint>

// Problem constants (from reference)
#define NN      50000
#define EE      800000
#define FD      128
#define GG      64
#define OUTD    64
#define NEXP    3
#define TEMP_F  101.0f

// HMMA MoE config: padded bf16 images, 128 rows x 136 cols (stride 272B)
#define IMG_ELEMS 17408            // 128*136
#define IMG_B     34816            // bytes per image
#define ROWSTRIDE 272              // bytes per row
#define MOE_SMEM  (6 * IMG_B + 1536)   // Ah Al | Bbuf0(hi,lo) Bbuf1(hi,lo) | bias[384]

#define SCAN_B    1024
#define SCAN_NBLK 64               // covers up to 65536 nodes

// ---------------- device scratch (no cudaMalloc allowed) ----------------
__device__ float g_dinv[NN];
__device__ int   g_degE[NN];          // in-edge count (no self loop)
__device__ int   g_fill[NN];
__device__ int   g_off[NN + 1];       // CSR row offsets
__device__ int   g_csr[EE];           // CSR src indices
__device__ int   g_bsum[SCAN_NBLK];   // per-block sums for 3-phase scan
__device__ float g_gate0[NN * NEXP];
__device__ float g_gate1[NN * NEXP];
__device__ float g_bufA[NN * FD];
__device__ float g_bufB[NN * FD];
__device__ int   g_is64;
// Pre-split weights: [layer(2)][expert(3)][hi,lo][128*136] bf16 (padded row-major [n][k])
__device__ __nv_bfloat16 g_wprep[2 * 3 * 2 * IMG_ELEMS];

// ---------------- helpers ----------------
__device__ __forceinline__ uint32_t smem_u32(const void* p) {
    uint32_t a;
    asm("{ .reg .u64 t; cvta.to.shared.u64 t, %1; cvt.u32.u64 %0, t; }" : "=r"(a) : "l"(p));
    return a;
}
__device__ __forceinline__ int load_idx(const void* p, long long i) {
    if (g_is64) return (int)((const long long*)p)[i];
    return ((const int*)p)[i];
}
__device__ __forceinline__ void cpa16(uint32_t dst, const void* src) {
    asm volatile("cp.async.cg.shared.global [%0], [%1], 16;" :: "r"(dst), "l"(src) : "memory");
}
#define CP_COMMIT() asm volatile("cp.async.commit_group;" ::: "memory")
#define CP_WAIT0()  asm volatile("cp.async.wait_group 0;" ::: "memory")

__device__ __forceinline__ void ldsm_x4(uint32_t (&r)[4], uint32_t addr) {
    asm volatile("ldmatrix.sync.aligned.m8n8.x4.shared.b16 {%0,%1,%2,%3}, [%4];"
                 : "=r"(r[0]), "=r"(r[1]), "=r"(r[2]), "=r"(r[3]) : "r"(addr));
}
__device__ __forceinline__ void ldsm_x2(uint32_t (&r)[2], uint32_t addr) {
    asm volatile("ldmatrix.sync.aligned.m8n8.x2.shared.b16 {%0,%1}, [%2];"
                 : "=r"(r[0]), "=r"(r[1]) : "r"(addr));
}
__device__ __forceinline__ void mma_bf16(float (&c)[4], const uint32_t (&a)[4],
                                         const uint32_t (&b)[2]) {
    asm volatile("mma.sync.aligned.m16n8k16.row.col.f32.bf16.bf16.f32 "
                 "{%0,%1,%2,%3}, {%4,%5,%6,%7}, {%8,%9}, {%0,%1,%2,%3};"
                 : "+f"(c[0]), "+f"(c[1]), "+f"(c[2]), "+f"(c[3])
                 : "r"(a[0]), "r"(a[1]), "r"(a[2]), "r"(a[3]), "r"(b[0]), "r"(b[1]));
}

// ---------------- graph-prep kernels ----------------
__global__ void detect_kernel(const int* p) {
    if (threadIdx.x == 0 && blockIdx.x == 0) {
        int all0 = 1;
        #pragma unroll
        for (int i = 1; i < 128; i += 2) if (p[i] != 0) all0 = 0;
        g_is64 = all0;
    }
}
__global__ void deg_init_kernel(int n) {
    int i = blockIdx.x * blockDim.x + threadIdx.x;
    if (i < n) { g_degE[i] = 0; g_fill[i] = 0; }
}
__global__ void deg_count_kernel(const void* ei, int E) {
    int i = blockIdx.x * blockDim.x + threadIdx.x;
    if (i >= E) return;
    atomicAdd(&g_degE[load_idx(ei, (long long)E + i)], 1);
}

// ---- 3-phase coalesced exclusive scan of g_degE into g_off ----
__global__ void __launch_bounds__(SCAN_B, 1) scan_reduce_kernel(int n) {
    __shared__ int sred[32];
    int i = blockIdx.x * SCAN_B + threadIdx.x;
    int v = (i < n) ? g_degE[i] : 0;
    #pragma unroll
    for (int o = 16; o > 0; o >>= 1) v += __shfl_down_sync(0xFFFFFFFFu, v, o);
    if ((threadIdx.x & 31) == 0) sred[threadIdx.x >> 5] = v;
    __syncthreads();
    if (threadIdx.x < 32) {
        int w = (threadIdx.x < SCAN_B / 32) ? sred[threadIdx.x] : 0;
        #pragma unroll
        for (int o = 16; o > 0; o >>= 1) w += __shfl_down_sync(0xFFFFFFFFu, w, o);
        if (threadIdx.x == 0) g_bsum[blockIdx.x] = w;
    }
}
__global__ void scan_mid_kernel(int nblk) {
    __shared__ int s[SCAN_NBLK];
    int t = threadIdx.x;
    int v = (t < nblk) ? g_bsum[t] : 0;
    s[t] = v;
    __syncthreads();
    #pragma unroll
    for (int o = 1; o < SCAN_NBLK; o <<= 1) {
        int u = (t >= o) ? s[t - o] : 0;
        __syncthreads();
        s[t] += u;
        __syncthreads();
    }
    g_bsum[t] = s[t] - v;     // exclusive
}
__global__ void __launch_bounds__(SCAN_B, 1) scan_apply_kernel(int n) {
    __shared__ int swarp[32];
    int i = blockIdx.x * SCAN_B + threadIdx.x;
    int lane = threadIdx.x & 31, wid = threadIdx.x >> 5;
    int v = (i < n) ? g_degE[i] : 0;
    // warp inclusive scan
    int inc = v;
    #pragma unroll
    for (int o = 1; o < 32; o <<= 1) {
        int u = __shfl_up_sync(0xFFFFFFFFu, inc, o);
        if (lane >= o) inc += u;
    }
    if (lane == 31) swarp[wid] = inc;
    __syncthreads();
    if (wid == 0) {
        int w = (lane < SCAN_B / 32) ? swarp[lane] : 0;
        int winc = w;
        #pragma unroll
        for (int o = 1; o < 32; o <<= 1) {
            int u = __shfl_up_sync(0xFFFFFFFFu, winc, o);
            if (lane >= o) winc += u;
        }
        swarp[lane] = winc - w;   // exclusive warp offsets
    }
    __syncthreads();
    int base = g_bsum[blockIdx.x] + swarp[wid];
    if (i < n) {
        g_off[i] = base + inc - v;
        if (i == n - 1) g_off[n] = base + inc;
    }
}

__global__ void scatter_kernel(const void* ei, int E) {
    int i = blockIdx.x * blockDim.x + threadIdx.x;
    if (i >= E) return;
    int s = load_idx(ei, i);
    int d = load_idx(ei, (long long)E + i);
    int pos = g_off[d] + atomicAdd(&g_fill[d], 1);
    g_csr[pos] = s;
}

// dinv + both layers' gates (fused per-node prep)
__global__ void node_prep_kernel(const float* __restrict__ top,
                                 const float* __restrict__ Wg0,
                                 const float* __restrict__ Wg1, int n) {
    int i = blockIdx.x * blockDim.x + threadIdx.x;
    if (i >= n) return;
    g_dinv[i] = rsqrtf((float)(g_degE[i] + 1));
    float t0 = top[i * 4 + 0], t1 = top[i * 4 + 1];
    float t2 = top[i * 4 + 2], t3 = top[i * 4 + 3];
    const float* wgs[2] = {Wg0, Wg1};
    float* outs[2] = {g_gate0, g_gate1};
    #pragma unroll
    for (int L = 0; L < 2; L++) {
        const float* Wg = wgs[L];
        float l[NEXP];
        #pragma unroll
        for (int e = 0; e < NEXP; e++)
            l[e] = (t0 * Wg[e * 4 + 0] + t1 * Wg[e * 4 + 1] +
                    t2 * Wg[e * 4 + 2] + t3 * Wg[e * 4 + 3]) * (1.0f / TEMP_F);
        float m = fmaxf(l[0], fmaxf(l[1], l[2]));
        float e0 = __expf(l[0] - m), e1 = __expf(l[1] - m), e2 = __expf(l[2] - m);
        float inv = 1.0f / (e0 + e1 + e2);
        outs[L][i * 3 + 0] = e0 * inv;
        outs[L][i * 3 + 1] = e1 * inv;
        outs[L][i * 3 + 2] = e2 * inv;
    }
}

// Pre-split + transpose weights. block b = L*3+e. dst[n][k] = W[k][n], hi/lo bf16.
__global__ void wprep_kernel(const float* __restrict__ W0, const float* __restrict__ W1) {
    int b = blockIdx.x;
    const float* src = (b < 3 ? W0 : W1) + (b % 3) * (FD * FD);
    __nv_bfloat16* dhi = g_wprep + (size_t)b * 2 * IMG_ELEMS;
    __nv_bfloat16* dlo = dhi + IMG_ELEMS;
    for (int i = threadIdx.x; i < FD * FD; i += blockDim.x) {
        int nidx = i >> 7, k = i & 127;
        float v = src[k * FD + nidx];
        __nv_bfloat16 h = __float2bfloat16(v);
        __nv_bfloat16 l = __float2bfloat16(v - __bfloat162float(h));
        dhi[nidx * 136 + k] = h;
        dlo[nidx * 136 + k] = l;
    }
}

// ---------------- CSR aggregation: pure gather, no atomics ----------------
__global__ void agg_csr_kernel(const float* __restrict__ h,
                               float* __restrict__ out, int n) {
    int r = (blockIdx.x * blockDim.x + threadIdx.x) >> 5;
    int lane = threadIdx.x & 31;
    if (r >= n) return;
    const float4* hp = (const float4*)h;
    float di = g_dinv[r];
    float4 self = hp[(size_t)r * 32 + lane];
    float s2 = di * di;
    float4 acc = make_float4(s2 * self.x, s2 * self.y, s2 * self.z, s2 * self.w);
    int e = g_off[r], e1 = g_off[r + 1];
    for (; e + 2 <= e1; e += 2) {
        int s0 = g_csr[e], s1 = g_csr[e + 1];
        float n0 = di * g_dinv[s0], n1 = di * g_dinv[s1];
        float4 v0 = hp[(size_t)s0 * 32 + lane];
        float4 v1 = hp[(size_t)s1 * 32 + lane];
        acc.x = fmaf(n0, v0.x, fmaf(n1, v1.x, acc.x));
        acc.y = fmaf(n0, v0.y, fmaf(n1, v1.y, acc.y));
        acc.z = fmaf(n0, v0.z, fmaf(n1, v1.z, acc.z));
        acc.w = fmaf(n0, v0.w, fmaf(n1, v1.w, acc.w));
    }
    if (e < e1) {
        int s0 = g_csr[e];
        float n0 = di * g_dinv[s0];
        float4 v0 = hp[(size_t)s0 * 32 + lane];
        acc.x = fmaf(n0, v0.x, acc.x);
        acc.y = fmaf(n0, v0.y, acc.y);
        acc.z = fmaf(n0, v0.z, acc.z);
        acc.w = fmaf(n0, v0.w, acc.w);
    }
    ((float4*)out)[(size_t)r * 32 + lane] = acc;
}

// ---------------- HMMA MoE layer ----------------
__global__ void __launch_bounds__(256, 1)
moe_hmma_kernel(const float* __restrict__ A, const __nv_bfloat16* __restrict__ wprepL,
                const float* __restrict__ bias, const float* __restrict__ gate,
                float* __restrict__ out, int n)
{
    extern __shared__ char smem[];
    const uint32_t sb = smem_u32(smem);
    const int t = threadIdx.x, lane = t & 31, wid = t >> 5;
    const int row0 = blockIdx.x * 128;
    float* sBias = (float*)(smem + 6 * IMG_B);

    for (int i = t; i < NEXP * FD; i += 256) sBias[i] = bias[i];

    #pragma unroll
    for (int i = 0; i < 16; i++) {
        int id = i * 256 + t;
        int r = id >> 5, c4 = id & 31, k0 = c4 * 4;
        int gr = row0 + r;
        float4 v = make_float4(0.f, 0.f, 0.f, 0.f);
        if (gr < n) v = reinterpret_cast<const float4*>(A)[(size_t)gr * 32 + c4];
        float vv[4] = {v.x, v.y, v.z, v.w};
        __nv_bfloat16 h[4], l[4];
        #pragma unroll
        for (int j = 0; j < 4; j++) {
            h[j] = __float2bfloat16(vv[j]);
            l[j] = __float2bfloat16(vv[j] - __bfloat162float(h[j]));
        }
        *(uint64_t*)(smem + r * ROWSTRIDE + k0 * 2)         = *(const uint64_t*)h;
        *(uint64_t*)(smem + IMG_B + r * ROWSTRIDE + k0 * 2) = *(const uint64_t*)l;
    }

    {
        uint32_t dst = sb + 2 * IMG_B;
        const char* src = (const char*)wprepL;
        for (int i = t; i < 2 * IMG_B / 16; i += 256) cpa16(dst + i * 16, src + i * 16);
        CP_COMMIT();
    }
    __syncthreads();
    CP_WAIT0();
    __syncthreads();

    const int m0 = (wid & 3) * 32, n0 = (wid >> 2) * 64;
    uint32_t aoff[2];
    #pragma unroll
    for (int mt = 0; mt < 2; mt++)
        aoff[mt] = (uint32_t)((m0 + mt * 16 + (lane & 7) + ((lane >> 3) & 1) * 8) * ROWSTRIDE
                              + (lane >> 4) * 16);
    const int l16 = lane & 15;
    uint32_t boff[8];
    #pragma unroll
    for (int nt = 0; nt < 8; nt++)
        boff[nt] = (uint32_t)((n0 + nt * 8 + (l16 & 7)) * ROWSTRIDE + (l16 >> 3) * 16);

    float o[2][8][4];
    #pragma unroll
    for (int mt = 0; mt < 2; mt++)
        #pragma unroll
        for (int nt = 0; nt < 8; nt++)
            #pragma unroll
            for (int j = 0; j < 4; j++) o[mt][nt][j] = 0.f;

    for (int e = 0; e < NEXP; e++) {
        const uint32_t bbase = sb + 2 * IMG_B + (uint32_t)(e & 1) * 2 * IMG_B;
        if (e < 2) {
            uint32_t dst = sb + 2 * IMG_B + (uint32_t)((e + 1) & 1) * 2 * IMG_B;
            const char* src = (const char*)(wprepL + (size_t)(e + 1) * 2 * IMG_ELEMS);
            for (int i = t; i < 2 * IMG_B / 16; i += 256) cpa16(dst + i * 16, src + i * 16);
            CP_COMMIT();
        }

        float c[2][8][4];
        #pragma unroll
        for (int mt = 0; mt < 2; mt++)
            #pragma unroll
            for (int nt = 0; nt < 8; nt++)
                #pragma unroll
                for (int j = 0; j < 4; j++) c[mt][nt][j] = 0.f;

        #pragma unroll 4
        for (int ks = 0; ks < 24; ks++) {
            int term = ks >> 3;
            uint32_t kb = (uint32_t)((ks & 7) * 32);
            uint32_t abase = sb + (term == 1 ? IMG_B : 0u) + kb;
            uint32_t bbs   = bbase + (term == 2 ? IMG_B : 0u) + kb;
            uint32_t a[2][4], b[8][2];
            #pragma unroll
            for (int mt = 0; mt < 2; mt++) ldsm_x4(a[mt], abase + aoff[mt]);
            #pragma unroll
            for (int nt = 0; nt < 8; nt++) ldsm_x2(b[nt], bbs + boff[nt]);
            #pragma unroll
            for (int mt = 0; mt < 2; mt++)
                #pragma unroll
                for (int nt = 0; nt < 8; nt++) mma_bf16(c[mt][nt], a[mt], b[nt]);
        }

        #pragma unroll
        for (int mt = 0; mt < 2; mt++) {
            int r0 = row0 + m0 + mt * 16 + (lane >> 2);
            int r1 = r0 + 8;
            float g0 = (r0 < n) ? gate[r0 * 3 + e] : 0.f;
            float g1 = (r1 < n) ? gate[r1 * 3 + e] : 0.f;
            #pragma unroll
            for (int nt = 0; nt < 8; nt++) {
                int nc = n0 + nt * 8 + 2 * (lane & 3);
                float b0v = sBias[e * 128 + nc], b1v = sBias[e * 128 + nc + 1];
                o[mt][nt][0] = fmaf(g0, fmaxf(c[mt][nt][0] + b0v, 0.f), o[mt][nt][0]);
                o[mt][nt][1] = fmaf(g0, fmaxf(c[mt][nt][1] + b1v, 0.f), o[mt][nt][1]);
                o[mt][nt][2] = fmaf(g1, fmaxf(c[mt][nt][2] + b0v, 0.f), o[mt][nt][2]);
                o[mt][nt][3] = fmaf(g1, fmaxf(c[mt][nt][3] + b1v, 0.f), o[mt][nt][3]);
            }
        }
        if (e < 2) CP_WAIT0();
        __syncthreads();
    }

    #pragma unroll
    for (int mt = 0; mt < 2; mt++) {
        int r0 = row0 + m0 + mt * 16 + (lane >> 2);
        int r1 = r0 + 8;
        #pragma unroll
        for (int nt = 0; nt < 8; nt++) {
            int nc = n0 + nt * 8 + 2 * (lane & 3);
            if (r0 < n)
                *(float2*)(out + (size_t)r0 * 128 + nc) = make_float2(o[mt][nt][0], o[mt][nt][1]);
            if (r1 < n)
                *(float2*)(out + (size_t)r1 * 128 + nc) = make_float2(o[mt][nt][2], o[mt][nt][3]);
        }
    }
}

// ---------------- fused pool + final (batch is sorted) ----------------
__device__ __forceinline__ int lbound_batch(const void* b, int n, long long key) {
    int lo = 0, hi = n;
    while (lo < hi) {
        int m = (lo + hi) >> 1;
        long long v = g_is64 ? ((const long long*)b)[m] : (long long)((const int*)b)[m];
        if (v < key) lo = m + 1; else hi = m;
    }
    return lo;
}

__global__ void pool_final_kernel(const float* __restrict__ h, const void* batch,
                                  const float* __restrict__ Wf,
                                  const float* __restrict__ bf,
                                  float* __restrict__ outp, int n) {
    __shared__ float sp[128];
    __shared__ int sLo, sHi;
    const int g = blockIdx.x, t = threadIdx.x;
    if (t == 0) sLo = lbound_batch(batch, n, g);
    if (t == 1) sHi = lbound_batch(batch, n, g + 1);
    __syncthreads();
    const int lo = sLo, hi = sHi;
    float s = 0.f;
    int r = lo;
    for (; r + 4 <= hi; r += 4) {
        s += h[(size_t)r * 128 + t] + h[(size_t)(r + 1) * 128 + t] +
             h[(size_t)(r + 2) * 128 + t] + h[(size_t)(r + 3) * 128 + t];
    }
    for (; r < hi; r++) s += h[(size_t)r * 128 + t];
    sp[t] = s / fmaxf((float)(hi - lo), 1.0f);
    __syncthreads();
    if (t < OUTD) {
        float acc = bf[t];
        #pragma unroll
        for (int k = 0; k < 128; k++) acc = fmaf(sp[k], Wf[k * OUTD + t], acc);
        outp[g * OUTD + t] = acc;
    }
}

// ---------------- launcher ----------------
extern "C" void kernel_launch(void* const* d_in, const int* in_sizes, int n_in,
                              void* d_out, int out_size) {
    const float* x    = (const float*)d_in[0];
    const float* top  = (const float*)d_in[1];
    const void*  ei   = d_in[2];
    const void*  batch= d_in[3];
    const float* W0   = (const float*)d_in[4];
    const float* b0   = (const float*)d_in[5];
    const float* Wg0  = (const float*)d_in[6];
    const float* W1   = (const float*)d_in[7];
    const float* b1   = (const float*)d_in[8];
    const float* Wg1  = (const float*)d_in[9];
    const float* Wf   = (const float*)d_in[10];
    const float* bf   = (const float*)d_in[11];
    float* out = (float*)d_out;

    const int N = in_sizes[0] / FD;
    const int E = in_sizes[2] / 2;

    // Device addresses for symbols passed as kernel args (R1 lesson: ATS makes
    // host-shadow symbol reads silently return host zeros).
    float* bufA;  cudaGetSymbolAddress((void**)&bufA,  g_bufA);
    float* bufB;  cudaGetSymbolAddress((void**)&bufB,  g_bufB);
    float* gate0; cudaGetSymbolAddress((void**)&gate0, g_gate0);
    float* gate1; cudaGetSymbolAddress((void**)&gate1, g_gate1);
    __nv_bfloat16* wprep; cudaGetSymbolAddress((void**)&wprep, g_wprep);

    cudaFuncSetAttribute(moe_hmma_kernel, cudaFuncAttributeMaxDynamicSharedMemorySize, MOE_SMEM);

    const int TPB = 256;
    int nb_n    = (N + TPB - 1) / TPB;
    int nb_e    = (E + TPB - 1) / TPB;
    int nb_aw   = (N * 32 + TPB - 1) / TPB;   // warp per row
    int nb_moe  = (N + 127) / 128;
    int nb_scan = (N + SCAN_B - 1) / SCAN_B;  // <= SCAN_NBLK

    // graph prep: degrees -> CSR -> dinv/gates
    detect_kernel<<<1, 32>>>((const int*)ei);
    deg_init_kernel<<<nb_n, TPB>>>(N);
    deg_count_kernel<<<nb_e, TPB>>>(ei, E);
    scan_reduce_kernel<<<nb_scan, SCAN_B>>>(N);
    scan_mid_kernel<<<1, SCAN_NBLK>>>(nb_scan);
    scan_apply_kernel<<<nb_scan, SCAN_B>>>(N);
    scatter_kernel<<<nb_e, TPB>>>(ei, E);
    node_prep_kernel<<<nb_n, TPB>>>(top, Wg0, Wg1, N);
    wprep_kernel<<<6, TPB>>>(W0, W1);

    // layer 0
    agg_csr_kernel<<<nb_aw, TPB>>>(x, bufA, N);
    moe_hmma_kernel<<<nb_moe, TPB, MOE_SMEM>>>(bufA, wprep, b0, gate0, bufB, N);
    // layer 1
    agg_csr_kernel<<<nb_aw, TPB>>>(bufB, bufA, N);
    moe_hmma_kernel<<<nb_moe, TPB, MOE_SMEM>>>(bufA, wprep + 3 * 2 * IMG_ELEMS, b1, gate1, bufB, N);

    // fused pooling + final projection
    pool_final_kernel<<<GG, 128>>>(bufB, batch, Wf, bf, out, N);
}

// round 8
// speedup vs baseline: 2.8123x; 1.0200x over previous
#include <cuda_runtime.h>
#include <cuda_bf16.h>
#include <cstdint>

// Problem constants (from reference)
#define NN      50000
#define EE      800000
#define FD      128
#define GG      64
#define OUTD    64
#define NEXP    3
#define TEMP_F  101.0f

// HMMA MoE config: padded bf16 images, 128 rows x 136 cols (stride 272B)
#define IMG_ELEMS 17408            // 128*136
#define IMG_B     34816            // bytes per image
#define ROWSTRIDE 272              // bytes per row
#define MOE_SMEM  (6 * IMG_B + 1536)   // Ah Al | Bbuf0(hi,lo) Bbuf1(hi,lo) | bias[384]

#define SCAN_B    1024
#define SCAN_NBLK 64               // covers up to 65536 nodes

// ---------------- device scratch (no cudaMalloc allowed) ----------------
__device__ float g_dinv[NN];
__device__ int   g_degE[NN];          // in-edge count (no self loop)
__device__ int   g_fill[NN];
__device__ int   g_off[NN + 1];       // CSR row offsets
__device__ int   g_csr[EE];           // CSR src indices
__device__ int   g_bsum[SCAN_NBLK];   // per-block sums for scan
__device__ float g_gate0[NN * NEXP];
__device__ float g_gate1[NN * NEXP];
__device__ float g_bufA[NN * FD];
__device__ float g_bufB[NN * FD];
__device__ int   g_is64;
// Pre-split weights: [layer(2)][expert(3)][hi,lo][128*136] bf16 (padded row-major [n][k])
__device__ __nv_bfloat16 g_wprep[2 * 3 * 2 * IMG_ELEMS];

// ---------------- helpers ----------------
__device__ __forceinline__ uint32_t smem_u32(const void* p) {
    uint32_t a;
    asm("{ .reg .u64 t; cvta.to.shared.u64 t, %1; cvt.u32.u64 %0, t; }" : "=r"(a) : "l"(p));
    return a;
}
__device__ __forceinline__ int load_idx(const void* p, long long i) {
    if (g_is64) return (int)((const long long*)p)[i];
    return ((const int*)p)[i];
}
__device__ __forceinline__ void cpa16(uint32_t dst, const void* src) {
    asm volatile("cp.async.cg.shared.global [%0], [%1], 16;" :: "r"(dst), "l"(src) : "memory");
}
#define CP_COMMIT() asm volatile("cp.async.commit_group;" ::: "memory")
#define CP_WAIT0()  asm volatile("cp.async.wait_group 0;" ::: "memory")

__device__ __forceinline__ void ldsm_x4(uint32_t (&r)[4], uint32_t addr) {
    asm volatile("ldmatrix.sync.aligned.m8n8.x4.shared.b16 {%0,%1,%2,%3}, [%4];"
                 : "=r"(r[0]), "=r"(r[1]), "=r"(r[2]), "=r"(r[3]) : "r"(addr));
}
__device__ __forceinline__ void ldsm_x2(uint32_t (&r)[2], uint32_t addr) {
    asm volatile("ldmatrix.sync.aligned.m8n8.x2.shared.b16 {%0,%1}, [%2];"
                 : "=r"(r[0]), "=r"(r[1]) : "r"(addr));
}
__device__ __forceinline__ void mma_bf16(float (&c)[4], const uint32_t (&a)[4],
                                         const uint32_t (&b)[2]) {
    asm volatile("mma.sync.aligned.m16n8k16.row.col.f32.bf16.bf16.f32 "
                 "{%0,%1,%2,%3}, {%4,%5,%6,%7}, {%8,%9}, {%0,%1,%2,%3};"
                 : "+f"(c[0]), "+f"(c[1]), "+f"(c[2]), "+f"(c[3])
                 : "r"(a[0]), "r"(a[1]), "r"(a[2]), "r"(a[3]), "r"(b[0]), "r"(b[1]));
}

// ---------------- fused prep0: deg/fill zero | weight split | idx-width detect ----------------
// Blocks [0, nbn): zero g_degE/g_fill. Blocks [nbn, nbn+6): weight prep.
__global__ void prep0_kernel(const int* eip, const float* __restrict__ W0,
                             const float* __restrict__ W1, int n, int nbn) {
    if ((int)blockIdx.x < nbn) {
        int i = blockIdx.x * blockDim.x + threadIdx.x;
        if (i < n) { g_degE[i] = 0; g_fill[i] = 0; }
        if (blockIdx.x == 0 && threadIdx.x == 0) {
            int all0 = 1;
            #pragma unroll
            for (int k = 1; k < 128; k += 2) if (eip[k] != 0) all0 = 0;
            g_is64 = all0;
        }
        return;
    }
    int b = blockIdx.x - nbn;                       // 0..5 = layer*3+expert
    const float* src = (b < 3 ? W0 : W1) + (b % 3) * (FD * FD);
    __nv_bfloat16* dhi = g_wprep + (size_t)b * 2 * IMG_ELEMS;
    __nv_bfloat16* dlo = dhi + IMG_ELEMS;
    for (int i = threadIdx.x; i < FD * FD; i += blockDim.x) {
        int nidx = i >> 7, k = i & 127;
        float v = src[k * FD + nidx];
        __nv_bfloat16 h = __float2bfloat16(v);
        __nv_bfloat16 l = __float2bfloat16(v - __bfloat162float(h));
        dhi[nidx * 136 + k] = h;
        dlo[nidx * 136 + k] = l;
    }
}

__global__ void deg_count_kernel(const void* ei, int E) {
    int i = blockIdx.x * blockDim.x + threadIdx.x;
    if (i >= E) return;
    atomicAdd(&g_degE[load_idx(ei, (long long)E + i)], 1);
}

// ---- scan phase 1: per-block sums ----
__global__ void __launch_bounds__(SCAN_B, 1) scan_reduce_kernel(int n) {
    __shared__ int sred[32];
    int i = blockIdx.x * SCAN_B + threadIdx.x;
    int v = (i < n) ? g_degE[i] : 0;
    #pragma unroll
    for (int o = 16; o > 0; o >>= 1) v += __shfl_down_sync(0xFFFFFFFFu, v, o);
    if ((threadIdx.x & 31) == 0) sred[threadIdx.x >> 5] = v;
    __syncthreads();
    if (threadIdx.x < 32) {
        int w = (threadIdx.x < SCAN_B / 32) ? sred[threadIdx.x] : 0;
        #pragma unroll
        for (int o = 16; o > 0; o >>= 1) w += __shfl_down_sync(0xFFFFFFFFu, w, o);
        if (threadIdx.x == 0) g_bsum[blockIdx.x] = w;
    }
}

// ---- scan phase 2 (fat): per-block scan of bsum + elementwise scan + dinv + gates ----
__global__ void __launch_bounds__(SCAN_B, 1)
scan_apply_kernel(const float* __restrict__ top, const float* __restrict__ Wg0,
                  const float* __restrict__ Wg1, int n, int nblk) {
    __shared__ int swarp[32];
    __shared__ int sbs[SCAN_NBLK];
    const int t = threadIdx.x;
    // every block scans the (<=64) block sums itself (replaces scan_mid kernel)
    if (t < SCAN_NBLK) sbs[t] = (t < nblk) ? g_bsum[t] : 0;
    __syncthreads();
    #pragma unroll
    for (int o = 1; o < SCAN_NBLK; o <<= 1) {
        int u = (t >= o && t < SCAN_NBLK) ? sbs[t - o] : 0;
        __syncthreads();
        if (t < SCAN_NBLK) sbs[t] += u;
        __syncthreads();
    }
    const int blockbase = (blockIdx.x == 0) ? 0 : sbs[blockIdx.x - 1];

    int i = blockIdx.x * SCAN_B + t;
    int lane = t & 31, wid = t >> 5;
    int v = (i < n) ? g_degE[i] : 0;
    int inc = v;
    #pragma unroll
    for (int o = 1; o < 32; o <<= 1) {
        int u = __shfl_up_sync(0xFFFFFFFFu, inc, o);
        if (lane >= o) inc += u;
    }
    if (lane == 31) swarp[wid] = inc;
    __syncthreads();
    if (wid == 0) {
        int w = (lane < SCAN_B / 32) ? swarp[lane] : 0;
        int winc = w;
        #pragma unroll
        for (int o = 1; o < 32; o <<= 1) {
            int u = __shfl_up_sync(0xFFFFFFFFu, winc, o);
            if (lane >= o) winc += u;
        }
        swarp[lane] = winc - w;
    }
    __syncthreads();
    int base = blockbase + swarp[wid];
    if (i < n) {
        g_off[i] = base + inc - v;
        if (i == n - 1) g_off[n] = base + inc;

        // fused node prep: dinv + both layers' gate softmax
        g_dinv[i] = rsqrtf((float)(v + 1));
        float t0 = top[i * 4 + 0], t1 = top[i * 4 + 1];
        float t2 = top[i * 4 + 2], t3 = top[i * 4 + 3];
        const float* wgs[2] = {Wg0, Wg1};
        float* outs[2] = {g_gate0, g_gate1};
        #pragma unroll
        for (int L = 0; L < 2; L++) {
            const float* Wg = wgs[L];
            float l[NEXP];
            #pragma unroll
            for (int e = 0; e < NEXP; e++)
                l[e] = (t0 * Wg[e * 4 + 0] + t1 * Wg[e * 4 + 1] +
                        t2 * Wg[e * 4 + 2] + t3 * Wg[e * 4 + 3]) * (1.0f / TEMP_F);
            float m = fmaxf(l[0], fmaxf(l[1], l[2]));
            float e0 = __expf(l[0] - m), e1 = __expf(l[1] - m), e2 = __expf(l[2] - m);
            float inv = 1.0f / (e0 + e1 + e2);
            outs[L][i * 3 + 0] = e0 * inv;
            outs[L][i * 3 + 1] = e1 * inv;
            outs[L][i * 3 + 2] = e2 * inv;
        }
    }
}

__global__ void scatter_kernel(const void* ei, int E) {
    int i = blockIdx.x * blockDim.x + threadIdx.x;
    if (i >= E) return;
    int s = load_idx(ei, i);
    int d = load_idx(ei, (long long)E + i);
    int pos = g_off[d] + atomicAdd(&g_fill[d], 1);
    g_csr[pos] = s;
}

// ---------------- CSR aggregation: pure gather, no atomics ----------------
__global__ void agg_csr_kernel(const float* __restrict__ h,
                               float* __restrict__ out, int n) {
    int r = (blockIdx.x * blockDim.x + threadIdx.x) >> 5;
    int lane = threadIdx.x & 31;
    if (r >= n) return;
    const float4* hp = (const float4*)h;
    float di = g_dinv[r];
    float4 self = hp[(size_t)r * 32 + lane];
    float s2 = di * di;
    float4 acc = make_float4(s2 * self.x, s2 * self.y, s2 * self.z, s2 * self.w);
    int e = g_off[r], e1 = g_off[r + 1];
    for (; e + 2 <= e1; e += 2) {
        int s0 = g_csr[e], s1 = g_csr[e + 1];
        float n0 = di * g_dinv[s0], n1 = di * g_dinv[s1];
        float4 v0 = hp[(size_t)s0 * 32 + lane];
        float4 v1 = hp[(size_t)s1 * 32 + lane];
        acc.x = fmaf(n0, v0.x, fmaf(n1, v1.x, acc.x));
        acc.y = fmaf(n0, v0.y, fmaf(n1, v1.y, acc.y));
        acc.z = fmaf(n0, v0.z, fmaf(n1, v1.z, acc.z));
        acc.w = fmaf(n0, v0.w, fmaf(n1, v1.w, acc.w));
    }
    if (e < e1) {
        int s0 = g_csr[e];
        float n0 = di * g_dinv[s0];
        float4 v0 = hp[(size_t)s0 * 32 + lane];
        acc.x = fmaf(n0, v0.x, acc.x);
        acc.y = fmaf(n0, v0.y, acc.y);
        acc.z = fmaf(n0, v0.z, acc.z);
        acc.w = fmaf(n0, v0.w, acc.w);
    }
    ((float4*)out)[(size_t)r * 32 + lane] = acc;
}

// ---------------- HMMA MoE layer ----------------
__global__ void __launch_bounds__(256, 1)
moe_hmma_kernel(const float* __restrict__ A, const __nv_bfloat16* __restrict__ wprepL,
                const float* __restrict__ bias, const float* __restrict__ gate,
                float* __restrict__ out, int n)
{
    extern __shared__ char smem[];
    const uint32_t sb = smem_u32(smem);
    const int t = threadIdx.x, lane = t & 31, wid = t >> 5;
    const int row0 = blockIdx.x * 128;
    float* sBias = (float*)(smem + 6 * IMG_B);

    for (int i = t; i < NEXP * FD; i += 256) sBias[i] = bias[i];

    #pragma unroll
    for (int i = 0; i < 16; i++) {
        int id = i * 256 + t;
        int r = id >> 5, c4 = id & 31, k0 = c4 * 4;
        int gr = row0 + r;
        float4 v = make_float4(0.f, 0.f, 0.f, 0.f);
        if (gr < n) v = reinterpret_cast<const float4*>(A)[(size_t)gr * 32 + c4];
        float vv[4] = {v.x, v.y, v.z, v.w};
        __nv_bfloat16 h[4], l[4];
        #pragma unroll
        for (int j = 0; j < 4; j++) {
            h[j] = __float2bfloat16(vv[j]);
            l[j] = __float2bfloat16(vv[j] - __bfloat162float(h[j]));
        }
        *(uint64_t*)(smem + r * ROWSTRIDE + k0 * 2)         = *(const uint64_t*)h;
        *(uint64_t*)(smem + IMG_B + r * ROWSTRIDE + k0 * 2) = *(const uint64_t*)l;
    }

    {
        uint32_t dst = sb + 2 * IMG_B;
        const char* src = (const char*)wprepL;
        for (int i = t; i < 2 * IMG_B / 16; i += 256) cpa16(dst + i * 16, src + i * 16);
        CP_COMMIT();
    }
    __syncthreads();
    CP_WAIT0();
    __syncthreads();

    const int m0 = (wid & 3) * 32, n0 = (wid >> 2) * 64;
    uint32_t aoff[2];
    #pragma unroll
    for (int mt = 0; mt < 2; mt++)
        aoff[mt] = (uint32_t)((m0 + mt * 16 + (lane & 7) + ((lane >> 3) & 1) * 8) * ROWSTRIDE
                              + (lane >> 4) * 16);
    const int l16 = lane & 15;
    uint32_t boff[8];
    #pragma unroll
    for (int nt = 0; nt < 8; nt++)
        boff[nt] = (uint32_t)((n0 + nt * 8 + (l16 & 7)) * ROWSTRIDE + (l16 >> 3) * 16);

    float o[2][8][4];
    #pragma unroll
    for (int mt = 0; mt < 2; mt++)
        #pragma unroll
        for (int nt = 0; nt < 8; nt++)
            #pragma unroll
            for (int j = 0; j < 4; j++) o[mt][nt][j] = 0.f;

    for (int e = 0; e < NEXP; e++) {
        const uint32_t bbase = sb + 2 * IMG_B + (uint32_t)(e & 1) * 2 * IMG_B;
        if (e < 2) {
            uint32_t dst = sb + 2 * IMG_B + (uint32_t)((e + 1) & 1) * 2 * IMG_B;
            const char* src = (const char*)(wprepL + (size_t)(e + 1) * 2 * IMG_ELEMS);
            for (int i = t; i < 2 * IMG_B / 16; i += 256) cpa16(dst + i * 16, src + i * 16);
            CP_COMMIT();
        }

        float c[2][8][4];
        #pragma unroll
        for (int mt = 0; mt < 2; mt++)
            #pragma unroll
            for (int nt = 0; nt < 8; nt++)
                #pragma unroll
                for (int j = 0; j < 4; j++) c[mt][nt][j] = 0.f;

        #pragma unroll 4
        for (int ks = 0; ks < 24; ks++) {
            int term = ks >> 3;
            uint32_t kb = (uint32_t)((ks & 7) * 32);
            uint32_t abase = sb + (term == 1 ? IMG_B : 0u) + kb;
            uint32_t bbs   = bbase + (term == 2 ? IMG_B : 0u) + kb;
            uint32_t a[2][4], b[8][2];
            #pragma unroll
            for (int mt = 0; mt < 2; mt++) ldsm_x4(a[mt], abase + aoff[mt]);
            #pragma unroll
            for (int nt = 0; nt < 8; nt++) ldsm_x2(b[nt], bbs + boff[nt]);
            #pragma unroll
            for (int mt = 0; mt < 2; mt++)
                #pragma unroll
                for (int nt = 0; nt < 8; nt++) mma_bf16(c[mt][nt], a[mt], b[nt]);
        }

        #pragma unroll
        for (int mt = 0; mt < 2; mt++) {
            int r0 = row0 + m0 + mt * 16 + (lane >> 2);
            int r1 = r0 + 8;
            float g0 = (r0 < n) ? gate[r0 * 3 + e] : 0.f;
            float g1 = (r1 < n) ? gate[r1 * 3 + e] : 0.f;
            #pragma unroll
            for (int nt = 0; nt < 8; nt++) {
                int nc = n0 + nt * 8 + 2 * (lane & 3);
                float b0v = sBias[e * 128 + nc], b1v = sBias[e * 128 + nc + 1];
                o[mt][nt][0] = fmaf(g0, fmaxf(c[mt][nt][0] + b0v, 0.f), o[mt][nt][0]);
                o[mt][nt][1] = fmaf(g0, fmaxf(c[mt][nt][1] + b1v, 0.f), o[mt][nt][1]);
                o[mt][nt][2] = fmaf(g1, fmaxf(c[mt][nt][2] + b0v, 0.f), o[mt][nt][2]);
                o[mt][nt][3] = fmaf(g1, fmaxf(c[mt][nt][3] + b1v, 0.f), o[mt][nt][3]);
            }
        }
        if (e < 2) CP_WAIT0();
        __syncthreads();
    }

    #pragma unroll
    for (int mt = 0; mt < 2; mt++) {
        int r0 = row0 + m0 + mt * 16 + (lane >> 2);
        int r1 = r0 + 8;
        #pragma unroll
        for (int nt = 0; nt < 8; nt++) {
            int nc = n0 + nt * 8 + 2 * (lane & 3);
            if (r0 < n)
                *(float2*)(out + (size_t)r0 * 128 + nc) = make_float2(o[mt][nt][0], o[mt][nt][1]);
            if (r1 < n)
                *(float2*)(out + (size_t)r1 * 128 + nc) = make_float2(o[mt][nt][2], o[mt][nt][3]);
        }
    }
}

// ---------------- fused pool + final (batch is sorted) ----------------
__device__ __forceinline__ int lbound_batch(const void* b, int n, long long key) {
    int lo = 0, hi = n;
    while (lo < hi) {
        int m = (lo + hi) >> 1;
        long long v = g_is64 ? ((const long long*)b)[m] : (long long)((const int*)b)[m];
        if (v < key) lo = m + 1; else hi = m;
    }
    return lo;
}

__global__ void pool_final_kernel(const float* __restrict__ h, const void* batch,
                                  const float* __restrict__ Wf,
                                  const float* __restrict__ bf,
                                  float* __restrict__ outp, int n) {
    __shared__ float sp[128];
    __shared__ int sLo, sHi;
    const int g = blockIdx.x, t = threadIdx.x;
    if (t == 0) sLo = lbound_batch(batch, n, g);
    if (t == 1) sHi = lbound_batch(batch, n, g + 1);
    __syncthreads();
    const int lo = sLo, hi = sHi;
    float s = 0.f;
    int r = lo;
    for (; r + 4 <= hi; r += 4) {
        s += h[(size_t)r * 128 + t] + h[(size_t)(r + 1) * 128 + t] +
             h[(size_t)(r + 2) * 128 + t] + h[(size_t)(r + 3) * 128 + t];
    }
    for (; r < hi; r++) s += h[(size_t)r * 128 + t];
    sp[t] = s / fmaxf((float)(hi - lo), 1.0f);
    __syncthreads();
    if (t < OUTD) {
        float acc = bf[t];
        #pragma unroll
        for (int k = 0; k < 128; k++) acc = fmaf(sp[k], Wf[k * OUTD + t], acc);
        outp[g * OUTD + t] = acc;
    }
}

// ---------------- launcher ----------------
extern "C" void kernel_launch(void* const* d_in, const int* in_sizes, int n_in,
                              void* d_out, int out_size) {
    const float* x    = (const float*)d_in[0];
    const float* top  = (const float*)d_in[1];
    const void*  ei   = d_in[2];
    const void*  batch= d_in[3];
    const float* W0   = (const float*)d_in[4];
    const float* b0   = (const float*)d_in[5];
    const float* Wg0  = (const float*)d_in[6];
    const float* W1   = (const float*)d_in[7];
    const float* b1   = (const float*)d_in[8];
    const float* Wg1  = (const float*)d_in[9];
    const float* Wf   = (const float*)d_in[10];
    const float* bf   = (const float*)d_in[11];
    float* out = (float*)d_out;

    const int N = in_sizes[0] / FD;
    const int E = in_sizes[2] / 2;

    // Device addresses for symbols passed as kernel args (R1 lesson: ATS makes
    // host-shadow symbol reads silently return host zeros).
    float* bufA;  cudaGetSymbolAddress((void**)&bufA,  g_bufA);
    float* bufB;  cudaGetSymbolAddress((void**)&bufB,  g_bufB);
    float* gate0; cudaGetSymbolAddress((void**)&gate0, g_gate0);
    float* gate1; cudaGetSymbolAddress((void**)&gate1, g_gate1);
    __nv_bfloat16* wprep; cudaGetSymbolAddress((void**)&wprep, g_wprep);

    cudaFuncSetAttribute(moe_hmma_kernel, cudaFuncAttributeMaxDynamicSharedMemorySize, MOE_SMEM);

    const int TPB = 256;
    int nb_n    = (N + TPB - 1) / TPB;
    int nb_e    = (E + TPB - 1) / TPB;
    int nb_aw   = (N * 32 + TPB - 1) / TPB;   // warp per row
    int nb_moe  = (N + 127) / 128;
    int nb_scan = (N + SCAN_B - 1) / SCAN_B;  // <= SCAN_NBLK

    // fused prep: zero degrees | split weights | detect idx width
    prep0_kernel<<<nb_n + 6, TPB>>>((const int*)ei, W0, W1, N, nb_n);
    deg_count_kernel<<<nb_e, TPB>>>(ei, E);
    scan_reduce_kernel<<<nb_scan, SCAN_B>>>(N);
    scan_apply_kernel<<<nb_scan, SCAN_B>>>(top, Wg0, Wg1, N, nb_scan);  // + dinv + gates
    scatter_kernel<<<nb_e, TPB>>>(ei, E);

    // layer 0
    agg_csr_kernel<<<nb_aw, TPB>>>(x, bufA, N);
    moe_hmma_kernel<<<nb_moe, TPB, MOE_SMEM>>>(bufA, wprep, b0, gate0, bufB, N);
    // layer 1
    agg_csr_kernel<<<nb_aw, TPB>>>(bufB, bufA, N);
    moe_hmma_kernel<<<nb_moe, TPB, MOE_SMEM>>>(bufA, wprep + 3 * 2 * IMG_ELEMS, b1, gate1, bufB, N);

    // fused pooling + final projection
    pool_final_kernel<<<GG, 128>>>(bufB, batch, Wf, bf, out, N);
}